// round 6
// baseline (speedup 1.0000x reference)
#include <cuda_runtime.h>
#include <cuda_bf16.h>
#include <cstdint>

// ---------------- problem constants ----------------
#define DIN 32
#define KSEQ 512
#define PD 64
#define DM 128
#define NL 4
#define PL 8
#define STR 4
#define DI 256          // 2*DM
#define DS 16
#define DC 4
#define DTR 8
#define NSEQ 127        // (KSEQ-PL)/STR + 1
#define BATCH 32
#define MSEQ (BATCH*PD)         // 2048 sequences
#define NTOK (MSEQ*NSEQ)        // 260096 tokens
#define XPJ (DTR + 2*DS)        // 40

// ---------------- scratch (device globals) ----------------
__device__ float g_h   [BATCH*KSEQ*PD];
__device__ float g_e   [NTOK*DM];           // residual
__device__ float g_uraw[NTOK*DI];           // in-proj u half (raw fp32)
__device__ float g_zg  [NTOK*DI];           // silu(z) gate (fp32)
__device__ float g_dbc [NTOK*XPJ];
__device__ float g_y1  [MSEQ];
// bf16 hi/lo operand buffers
__device__ __nv_bfloat16 g_rh[NTOK*DM];     // rms-normed residual (in-proj A)
__device__ __nv_bfloat16 g_rl[NTOK*DM];
__device__ __nv_bfloat16 g_ah[NTOK*DI];     // gated scan out (out-proj A)
__device__ __nv_bfloat16 g_al[NTOK*DI];
__device__ __nv_bfloat16 g_uh[NTOK*DI];     // conv+silu out (xproj A)
__device__ __nv_bfloat16 g_ul[NTOK*DI];
// transposed hi/lo weights [n][k]
__device__ __nv_bfloat16 g_wih[NL*2*DI*DM];
__device__ __nv_bfloat16 g_wil[NL*2*DI*DM];
__device__ __nv_bfloat16 g_wxh[NL*64*DI];
__device__ __nv_bfloat16 g_wxl[NL*64*DI];
__device__ __nv_bfloat16 g_woh[NL*DM*DI];
__device__ __nv_bfloat16 g_wol[NL*DM*DI];

// ---------------- FMA-only transcendentals ----------
__device__ __forceinline__ float fexp(float x) {
    x = fminf(fmaxf(x, -87.0f), 87.0f);
    float t  = x * 1.4426950408889634f;
    float fi = floorf(t);
    float f  = t - fi;
    float p  = 1.5252733804059841e-05f;
    p = fmaf(p, f, 1.5403530393381608e-04f);
    p = fmaf(p, f, 1.3333558146428443e-03f);
    p = fmaf(p, f, 9.6181291076284770e-03f);
    p = fmaf(p, f, 5.5504108664821580e-02f);
    p = fmaf(p, f, 2.4022650695910070e-01f);
    p = fmaf(p, f, 6.9314718055994530e-01f);
    p = fmaf(p, f, 1.0f);
    int ei = (int)fi;
    float sc = __int_as_float((ei + 127) << 23);
    return p * sc;
}

__device__ __forceinline__ float flog(float x) {
    int ix = __float_as_int(x);
    int e  = ((ix >> 23) & 0xFF) - 127;
    float m = __int_as_float((ix & 0x007FFFFF) | 0x3F800000);
    if (m > 1.41421356f) { m *= 0.5f; e += 1; }
    float f = m - 1.0f;
    float z = f * f;
    float p = 7.0376836292e-2f;
    p = fmaf(p, f, -1.1514610310e-1f);
    p = fmaf(p, f,  1.1676998740e-1f);
    p = fmaf(p, f, -1.2420140846e-1f);
    p = fmaf(p, f,  1.4249322787e-1f);
    p = fmaf(p, f, -1.6668057665e-1f);
    p = fmaf(p, f,  2.0000714765e-1f);
    p = fmaf(p, f, -2.4999993993e-1f);
    p = fmaf(p, f,  3.3333331174e-1f);
    float r = f * z * p - 0.5f * z + f;
    return fmaf((float)e, 0.693147180559945f, r);
}

__device__ __forceinline__ float frcp_pos(float a) {
    float x = __int_as_float(0x7EF311C3 - __float_as_int(a));
    x = x * (2.0f - a * x);
    x = x * (2.0f - a * x);
    x = x * (2.0f - a * x);
    return x;
}

__device__ __forceinline__ float fsigmoid(float x) { return frcp_pos(1.0f + fexp(-x)); }
__device__ __forceinline__ float fsilu(float x)    { return x * fsigmoid(x); }

__device__ __forceinline__ float block_reduce_128(float v, float* red) {
    #pragma unroll
    for (int o = 16; o > 0; o >>= 1) v += __shfl_xor_sync(0xffffffffu, v, o);
    int w = threadIdx.x >> 5;
    __syncthreads();
    if ((threadIdx.x & 31) == 0) red[w] = v;
    __syncthreads();
    return red[0] + red[1] + red[2] + red[3];
}

// ---------------- MMA helpers ----------
__device__ __forceinline__ uint32_t smem_u32(const void* p) {
    uint32_t a;
    asm("{ .reg .u64 t; cvta.to.shared.u64 t, %1; cvt.u32.u64 %0, t; }" : "=r"(a) : "l"(p));
    return a;
}
__device__ __forceinline__ void ldm4(uint32_t* r, uint32_t addr) {
    asm volatile("ldmatrix.sync.aligned.m8n8.x4.shared.b16 {%0,%1,%2,%3}, [%4];"
                 : "=r"(r[0]), "=r"(r[1]), "=r"(r[2]), "=r"(r[3]) : "r"(addr));
}
__device__ __forceinline__ void mma16816(float* c, const uint32_t* a, const uint32_t* b) {
    asm volatile(
        "mma.sync.aligned.m16n8k16.row.col.f32.bf16.bf16.f32 "
        "{%0,%1,%2,%3}, {%4,%5,%6,%7}, {%8,%9}, {%0,%1,%2,%3};"
        : "+f"(c[0]), "+f"(c[1]), "+f"(c[2]), "+f"(c[3])
        : "r"(a[0]), "r"(a[1]), "r"(a[2]), "r"(a[3]), "r"(b[0]), "r"(b[1]));
}
__device__ __forceinline__ void cp16(uint32_t dst, const void* src) {
    asm volatile("cp.async.cg.shared.global [%0], [%1], 16;" :: "r"(dst), "l"(src));
}
__device__ __forceinline__ void cp_commit() { asm volatile("cp.async.commit_group;"); }

__device__ __forceinline__ uint32_t pack_hi2(float x, float y) {
    __nv_bfloat16 hx = __float2bfloat16(x), hy = __float2bfloat16(y);
    return (uint32_t)__bfloat16_as_ushort(hx) | ((uint32_t)__bfloat16_as_ushort(hy) << 16);
}
__device__ __forceinline__ uint32_t pack_lo2(float x, float y, uint32_t hi) {
    float hx = __bfloat162float(__ushort_as_bfloat16((unsigned short)(hi & 0xFFFF)));
    float hy = __bfloat162float(__ushort_as_bfloat16((unsigned short)(hi >> 16)));
    __nv_bfloat16 lx = __float2bfloat16(x - hx), ly = __float2bfloat16(y - hy);
    return (uint32_t)__bfloat16_as_ushort(lx) | ((uint32_t)__bfloat16_as_ushort(ly) << 16);
}

// ---------------- double-buffered bf16 hi/lo tensor-core GEMM ----------------
// MODE 0: C[M,Nvalid] = A@B^T (masked store)
// MODE 2: split in-proj: cols<DI -> C (raw fp32), cols>=DI -> silu -> C2
// MODE 3: C += A@B^T (residual e), then fused RMS -> Eh/El (bf16 hi/lo) with nw
#define GP 80    // smem row pitch bytes (40 bf16; conflict-free ldmatrix)
template<int NTILE, int MODE>
__global__ void __launch_bounds__(256, 2) mma_gemm(
    const __nv_bfloat16* __restrict__ Ah, const __nv_bfloat16* __restrict__ Al, int lda,
    const __nv_bfloat16* __restrict__ Bh, const __nv_bfloat16* __restrict__ Bl, int ldb,
    float* __restrict__ C, int ldc, float* __restrict__ C2,
    __nv_bfloat16* __restrict__ Eh, __nv_bfloat16* __restrict__ El,
    const float* __restrict__ nw, int Nvalid, int K)
{
    constexpr int WARP_N = NTILE / 2;
    constexpr int NT8    = WARP_N / 8;
    constexpr int ASZ    = 2 * 128 * GP;
    constexpr int SS     = ASZ + 2 * NTILE * GP;
    extern __shared__ char smem[];
    const uint32_t sb = smem_u32(smem);
    const int tid  = threadIdx.x;
    const int wid  = tid >> 5, lane = tid & 31;
    const int row0 = blockIdx.y * 128;
    const int col0 = blockIdx.x * NTILE;
    const int m_off = (wid & 3) * 32;
    const int n_off = (wid >> 2) * WARP_N;

    const int j = lane >> 3, r = lane & 7;
    const int a_loff = ((j & 1) * 8 + r) * GP + (j >> 1) * 16;
    const int b_loff = ((j >> 1) * 8 + r) * GP + (j & 1) * 16;

    float acc[2][NT8][4];
    #pragma unroll
    for (int mt = 0; mt < 2; mt++)
        #pragma unroll
        for (int nt = 0; nt < NT8; nt++)
            #pragma unroll
            for (int i = 0; i < 4; i++) acc[mt][nt][i] = 0.f;

    auto stage = [&](int st, int k0) {
        uint32_t base = sb + st * SS;
        #pragma unroll
        for (int i = 0; i < 4; i++) {
            int idx = tid + i * 256;
            int h = idx >> 9, rr = (idx >> 2) & 127, c = idx & 3;
            const __nv_bfloat16* src = (h ? Al : Ah) + (size_t)(row0 + rr) * lda + k0 + c * 8;
            cp16(base + h * (128 * GP) + rr * GP + c * 16, src);
        }
        #pragma unroll
        for (int i = 0; i < NTILE / 32; i++) {
            int idx = tid + i * 256;
            int h = idx >= NTILE * 4;
            int id2 = idx & (NTILE * 4 - 1);
            int n = id2 >> 2, c = id2 & 3;
            const __nv_bfloat16* src = (h ? Bl : Bh) + (size_t)(col0 + n) * ldb + k0 + c * 8;
            cp16(base + ASZ + h * (NTILE * GP) + n * GP + c * 16, src);
        }
        cp_commit();
    };

    const int nk = K / 32;
    stage(0, 0);
    for (int i = 0; i < nk; i++) {
        if (i + 1 < nk) {
            stage((i + 1) & 1, (i + 1) * 32);
            asm volatile("cp.async.wait_group 1;" ::: "memory");
        } else {
            asm volatile("cp.async.wait_group 0;" ::: "memory");
        }
        __syncthreads();
        uint32_t base = sb + (i & 1) * SS;
        uint32_t sA[2] = { base, base + 128 * GP };
        uint32_t sB[2] = { base + ASZ, base + ASZ + NTILE * GP };
        #pragma unroll
        for (int kk = 0; kk < 32; kk += 16) {
            uint32_t afr[2][2][4];
            #pragma unroll
            for (int mt = 0; mt < 2; mt++)
                #pragma unroll
                for (int h = 0; h < 2; h++)
                    ldm4(afr[mt][h], sA[h] + (m_off + mt * 16) * GP + kk * 2 + a_loff);
            uint32_t bfr[NTILE / 32][2][4];
            #pragma unroll
            for (int np = 0; np < NTILE / 32; np++)
                #pragma unroll
                for (int h = 0; h < 2; h++)
                    ldm4(bfr[np][h], sB[h] + (n_off + np * 16) * GP + kk * 2 + b_loff);
            #pragma unroll
            for (int mt = 0; mt < 2; mt++)
                #pragma unroll
                for (int nt = 0; nt < NT8; nt++) {
                    const uint32_t* bh = &bfr[nt >> 1][0][(nt & 1) * 2];
                    const uint32_t* bl = &bfr[nt >> 1][1][(nt & 1) * 2];
                    mma16816(acc[mt][nt], afr[mt][0], bh);
                    mma16816(acc[mt][nt], afr[mt][0], bl);
                    mma16816(acc[mt][nt], afr[mt][1], bh);
                }
        }
        __syncthreads();
    }

    const int lr = lane >> 2, lq = lane & 3;
    if (MODE == 0) {
        #pragma unroll
        for (int mt = 0; mt < 2; mt++)
            #pragma unroll
            for (int nt = 0; nt < NT8; nt++) {
                int rbase = row0 + m_off + mt * 16 + lr;
                int cc = col0 + n_off + nt * 8 + lq * 2;
                if (cc < Nvalid) {
                    *(float2*)(C + (size_t)rbase * ldc + cc) =
                        make_float2(acc[mt][nt][0], acc[mt][nt][1]);
                    *(float2*)(C + (size_t)(rbase + 8) * ldc + cc) =
                        make_float2(acc[mt][nt][2], acc[mt][nt][3]);
                }
            }
    } else if (MODE == 2) {
        #pragma unroll
        for (int mt = 0; mt < 2; mt++)
            #pragma unroll
            for (int nt = 0; nt < NT8; nt++) {
                int rbase = row0 + m_off + mt * 16 + lr;
                int cc = col0 + n_off + nt * 8 + lq * 2;
                if (cc < DI) {
                    *(float2*)(C + (size_t)rbase * DI + cc) =
                        make_float2(acc[mt][nt][0], acc[mt][nt][1]);
                    *(float2*)(C + (size_t)(rbase + 8) * DI + cc) =
                        make_float2(acc[mt][nt][2], acc[mt][nt][3]);
                } else {
                    int cz = cc - DI;
                    *(float2*)(C2 + (size_t)rbase * DI + cz) =
                        make_float2(fsilu(acc[mt][nt][0]), fsilu(acc[mt][nt][1]));
                    *(float2*)(C2 + (size_t)(rbase + 8) * DI + cz) =
                        make_float2(fsilu(acc[mt][nt][2]), fsilu(acc[mt][nt][3]));
                }
            }
    } else {  // MODE 3: residual ACC + fused RMS -> Eh/El
        float* ssq = (float*)smem;   // 256 floats; stage buffers dead
        const int half = wid >> 2;
        float part[4] = {0.f, 0.f, 0.f, 0.f};
        #pragma unroll
        for (int mt = 0; mt < 2; mt++)
            #pragma unroll
            for (int nt = 0; nt < NT8; nt++) {
                int r0g = row0 + m_off + mt * 16 + lr;
                int cc = n_off + nt * 8 + lq * 2;       // col0 == 0 (NTILE==DM)
                float2* p0 = (float2*)(C + (size_t)r0g * ldc + cc);
                float2* p1 = (float2*)(C + (size_t)(r0g + 8) * ldc + cc);
                float2 o0 = *p0, o1 = *p1;
                o0.x += acc[mt][nt][0]; o0.y += acc[mt][nt][1];
                o1.x += acc[mt][nt][2]; o1.y += acc[mt][nt][3];
                *p0 = o0; *p1 = o1;
                acc[mt][nt][0] = o0.x; acc[mt][nt][1] = o0.y;
                acc[mt][nt][2] = o1.x; acc[mt][nt][3] = o1.y;
                part[mt * 2 + 0] += o0.x * o0.x + o0.y * o0.y;
                part[mt * 2 + 1] += o1.x * o1.x + o1.y * o1.y;
            }
        #pragma unroll
        for (int s = 0; s < 4; s++) {
            part[s] += __shfl_xor_sync(0xffffffffu, part[s], 1);
            part[s] += __shfl_xor_sync(0xffffffffu, part[s], 2);
        }
        if (lq == 0) {
            ssq[half * 128 + m_off + lr]      = part[0];
            ssq[half * 128 + m_off + lr + 8]  = part[1];
            ssq[half * 128 + m_off + lr + 16] = part[2];
            ssq[half * 128 + m_off + lr + 24] = part[3];
        }
        __syncthreads();
        #pragma unroll
        for (int mt = 0; mt < 2; mt++) {
            int rr = m_off + mt * 16 + lr;
            float sc0 = rsqrtf((ssq[rr]     + ssq[128 + rr])     * (1.0f / DM) + 1e-5f);
            float sc1 = rsqrtf((ssq[rr + 8] + ssq[128 + rr + 8]) * (1.0f / DM) + 1e-5f);
            int r0g = row0 + rr;
            #pragma unroll
            for (int nt = 0; nt < NT8; nt++) {
                int cc = n_off + nt * 8 + lq * 2;
                float w0 = nw[cc], w1 = nw[cc + 1];
                float a0 = acc[mt][nt][0] * sc0 * w0, a1 = acc[mt][nt][1] * sc0 * w1;
                float a2 = acc[mt][nt][2] * sc1 * w0, a3 = acc[mt][nt][3] * sc1 * w1;
                uint32_t h0 = pack_hi2(a0, a1), l0 = pack_lo2(a0, a1, h0);
                uint32_t h1 = pack_hi2(a2, a3), l1 = pack_lo2(a2, a3, h1);
                *(uint32_t*)(Eh + (size_t)r0g * DM + cc)       = h0;
                *(uint32_t*)(El + (size_t)r0g * DM + cc)       = l0;
                *(uint32_t*)(Eh + (size_t)(r0g + 8) * DM + cc) = h1;
                *(uint32_t*)(El + (size_t)(r0g + 8) * DM + cc) = l1;
            }
        }
    }
}

// ---------------- weight convert+transpose (all layers in one launch) ----------
__global__ void wconv_kernel(const float* __restrict__ src, __nv_bfloat16* __restrict__ dh,
                             __nv_bfloat16* __restrict__ dl, int K, int Nsrc, int Npad) {
    int l = blockIdx.y;
    src += (size_t)l * K * Nsrc;
    dh  += (size_t)l * Npad * K;
    dl  += (size_t)l * Npad * K;
    int idx = blockIdx.x * 256 + threadIdx.x;
    if (idx >= Npad * K) return;
    int n = idx / K, k = idx - n * K;
    float v = (n < Nsrc) ? src[(size_t)k * Nsrc + n] : 0.f;
    __nv_bfloat16 h = __float2bfloat16(v);
    dh[idx] = h;
    dl[idx] = __float2bfloat16(v - __bfloat162float(h));
}

// ---------------- 1) front: h = LN(x @ proj_w + proj_b) ----------------
__global__ void front_kernel(const float* __restrict__ x,  const float* __restrict__ pw,
                             const float* __restrict__ pb, const float* __restrict__ lw,
                             const float* __restrict__ lb) {
    int row = blockIdx.x;
    int pd  = threadIdx.x;         // 64
    __shared__ float xr[DIN];
    __shared__ float red[2];
    if (pd < DIN) xr[pd] = x[row * DIN + pd];
    __syncthreads();
    float acc = pb[pd];
    #pragma unroll
    for (int i = 0; i < DIN; i++) acc = fmaf(xr[i], pw[i * PD + pd], acc);
    float s = acc;
    #pragma unroll
    for (int o = 16; o > 0; o >>= 1) s += __shfl_xor_sync(0xffffffffu, s, o);
    if ((pd & 31) == 0) red[pd >> 5] = s;
    __syncthreads();
    float mu = (red[0] + red[1]) * (1.0f / PD);
    __syncthreads();
    float d = acc - mu;
    float q = d * d;
    #pragma unroll
    for (int o = 16; o > 0; o >>= 1) q += __shfl_xor_sync(0xffffffffu, q, o);
    if ((pd & 31) == 0) red[pd >> 5] = q;
    __syncthreads();
    float var = (red[0] + red[1]) * (1.0f / PD);
    g_h[row * PD + pd] = d * rsqrtf(var + 1e-5f) * lw[pd] + lb[pd];
}

// ---------------- 2) patch embed + fused layer-0 RMS ----------------
__global__ void patch_kernel(const float* __restrict__ patch_w, const float* __restrict__ patch_b,
                             const float* __restrict__ nw0) {
    int n  = blockIdx.x;
    int m  = blockIdx.y;
    int dm = threadIdx.x;          // 128
    int b  = m >> 6, pd = m & 63;
    __shared__ float hv[PL];
    __shared__ float red[4];
    if (dm < PL) hv[dm] = g_h[(b * KSEQ + n * STR + dm) * PD + pd];
    __syncthreads();
    float acc = patch_b[dm];
    #pragma unroll
    for (int pl = 0; pl < PL; pl++) acc = fmaf(hv[pl], patch_w[pl * DM + dm], acc);
    size_t tok = (size_t)m * NSEQ + n;
    g_e[tok * DM + dm] = acc;
    float ss = block_reduce_128(acc * acc, red);
    float sc = rsqrtf(ss * (1.0f / DM) + 1e-5f);
    float a = acc * sc * nw0[dm];
    __nv_bfloat16 h = __float2bfloat16(a);
    g_rh[tok * DM + dm] = h;
    g_rl[tok * DM + dm] = __float2bfloat16(a - __bfloat162float(h));
}

// ---------------- 4) depthwise causal conv + SiLU -> bf16 hi/lo ----------------
__global__ void conv_kernel(const float* __restrict__ cw, const float* __restrict__ cb) {
    int m = blockIdx.x;            // MSEQ
    int d = threadIdx.x;           // DI
    float w0 = cw[d * DC + 0], w1 = cw[d * DC + 1], w2 = cw[d * DC + 2], w3 = cw[d * DC + 3];
    float bias = cb[d];
    float x0 = 0.f, x1 = 0.f, x2 = 0.f;
    const float* up = g_uraw + (size_t)m * NSEQ * DI + d;
    size_t ob = (size_t)m * NSEQ * DI + d;
    for (int t = 0; t < NSEQ; t++) {
        float xt = up[(size_t)t * DI];
        float uc = bias;
        uc = fmaf(x0, w0, uc);
        uc = fmaf(x1, w1, uc);
        uc = fmaf(x2, w2, uc);
        uc = fmaf(xt, w3, uc);
        float u = fsilu(uc);
        __nv_bfloat16 h = __float2bfloat16(u);
        g_uh[ob + (size_t)t * DI] = h;
        g_ul[ob + (size_t)t * DI] = __float2bfloat16(u - __bfloat162float(h));
        x0 = x1; x1 = x2; x2 = xt;
    }
}

// ---------------- 5) fused dt-proj + softplus + scan + gate ----------
__global__ void scan_kernel(const float* __restrict__ dtw, const float* __restrict__ dtbp,
                            const float* __restrict__ alog, const float* __restrict__ dpp) {
    int m = blockIdx.x;            // MSEQ
    int d = threadIdx.x;           // DI
    __shared__ float buf[2][8][XPJ];
    float wreg[DTR];
    #pragma unroll
    for (int i = 0; i < DTR; i++) wreg[i] = dtw[i * DI + d];
    float dtb = dtbp[d];
    float Dpv = dpp[d];
    bool fast = true;
    #pragma unroll
    for (int s = 0; s < DS; s++) {
        float as = -fexp(alog[d * DS + s]);
        fast = fast && (fabsf(as + (float)(s + 1)) < 1e-3f);
    }
    float hst[DS];
    #pragma unroll
    for (int s = 0; s < DS; s++) hst[s] = 0.f;

    const float* dbc = g_dbc + (size_t)m * NSEQ * XPJ;
    for (int idx = d; idx < 8 * XPJ; idx += DI)
        buf[0][idx / XPJ][idx % XPJ] = dbc[idx];
    __syncthreads();

    const int NTILES = (NSEQ + 7) / 8;   // 16
    for (int jt = 0; jt < NTILES; jt++) {
        int t0 = jt * 8;
        int cnt = min(8, NSEQ - t0);
        if (jt + 1 < NTILES) {
            int t1 = t0 + 8;
            int cnt1 = min(8, NSEQ - t1);
            for (int idx = d; idx < cnt1 * XPJ; idx += DI)
                buf[(jt + 1) & 1][idx / XPJ][idx % XPJ] = dbc[(size_t)t1 * XPJ + idx];
        }
        const float* bj = &buf[jt & 1][0][0];
        for (int tt = 0; tt < cnt; tt++) {
            int t = t0 + tt;
            const float* s40 = bj + tt * XPJ;
            size_t off = ((size_t)m * NSEQ + t) * DI + d;
            float u_td = __bfloat162float(g_uh[off]) + __bfloat162float(g_ul[off]);
            float v = dtb;
            #pragma unroll
            for (int i = 0; i < DTR; i++) v = fmaf(s40[i], wreg[i], v);
            float e1 = fexp(v);
            float delta = (v > 20.f) ? v : flog(1.0f + e1);
            float du = delta * u_td;
            float y = 0.f;
            if (fast) {
                float rr = frcp_pos(1.0f + e1);      // exp(-softplus(v)) = 1/(1+e^v)
                float p = rr;
                #pragma unroll
                for (int s = 0; s < DS; s++) {
                    hst[s] = fmaf(p, hst[s], du * s40[DTR + s]);
                    y = fmaf(hst[s], s40[DTR + DS + s], y);
                    p *= rr;
                }
            } else {
                #pragma unroll
                for (int s = 0; s < DS; s++) {
                    float as = -fexp(alog[d * DS + s]);
                    float dA = fexp(delta * as);
                    hst[s] = fmaf(dA, hst[s], du * s40[DTR + s]);
                    y = fmaf(hst[s], s40[DTR + DS + s], y);
                }
            }
            float yo = fmaf(u_td, Dpv, y);
            float yg = yo * g_zg[off];
            __nv_bfloat16 h = __float2bfloat16(yg);
            g_ah[off] = h;
            g_al[off] = __float2bfloat16(yg - __bfloat162float(h));
        }
        __syncthreads();
    }
}

// ---------------- 6) final RMS + bb dot (warp-per-token) ----------------
__global__ void bb_kernel(const float* __restrict__ fnw, const float* __restrict__ bbw,
                          const float* __restrict__ bbb) {
    int m = blockIdx.x;
    int tid = threadIdx.x;         // 128
    int w = tid >> 5, lane = tid & 31;
    __shared__ float red[4];
    float4 fw = *(const float4*)(fnw + lane * 4);
    float acc0 = 0.f, acc1 = 0.f, acc2 = 0.f, acc3 = 0.f;
    for (int n = w; n < NSEQ; n += 4) {
        const float* er = g_e + ((size_t)m * NSEQ + n) * DM;
        float4 v = *(const float4*)(er + lane * 4);
        float ss = v.x * v.x + v.y * v.y + v.z * v.z + v.w * v.w;
        #pragma unroll
        for (int o = 16; o > 0; o >>= 1) ss += __shfl_xor_sync(0xffffffffu, ss, o);
        float sc = rsqrtf(ss * (1.0f / DM) + 1e-5f);
        float4 bw = *(const float4*)(bbw + n * DM + lane * 4);
        acc0 = fmaf(v.x * sc * fw.x, bw.x, acc0);
        acc1 = fmaf(v.y * sc * fw.y, bw.y, acc1);
        acc2 = fmaf(v.z * sc * fw.z, bw.z, acc2);
        acc3 = fmaf(v.w * sc * fw.w, bw.w, acc3);
    }
    float tot = acc0 + acc1 + acc2 + acc3;
    #pragma unroll
    for (int o = 16; o > 0; o >>= 1) tot += __shfl_xor_sync(0xffffffffu, tot, o);
    if (lane == 0) red[w] = tot;
    __syncthreads();
    if (tid == 0) g_y1[m] = red[0] + red[1] + red[2] + red[3] + bbb[0];
}

// ---------------- 7) head ----------------
__global__ void head_kernel(const float* __restrict__ hw, const float* __restrict__ hb,
                            float* __restrict__ out) {
    int t = threadIdx.x;           // 64
    int b = t >> 1, jj = t & 1;
    float acc = hb[jj];
    #pragma unroll
    for (int p = 0; p < PD; p++) acc = fmaf(g_y1[b * PD + p], hw[p * 2 + jj], acc);
    out[b * 2 + jj] = acc;
}

// ---------------- launch ----------------
extern "C" void kernel_launch(void* const* d_in, const int* in_sizes, int n_in,
                              void* d_out, int out_size) {
    const float* x       = (const float*)d_in[0];
    const float* proj_w  = (const float*)d_in[1];
    const float* proj_b  = (const float*)d_in[2];
    const float* ln_w    = (const float*)d_in[3];
    const float* ln_b    = (const float*)d_in[4];
    const float* patch_w = (const float*)d_in[5];
    const float* patch_b = (const float*)d_in[6];
    const float* in_w    = (const float*)d_in[7];
    const float* conv_w  = (const float*)d_in[8];
    const float* conv_b  = (const float*)d_in[9];
    const float* xproj_w = (const float*)d_in[10];
    const float* dt_w    = (const float*)d_in[11];
    const float* dt_b    = (const float*)d_in[12];
    const float* A_log   = (const float*)d_in[13];
    const float* Dp      = (const float*)d_in[14];
    const float* out_w   = (const float*)d_in[15];
    const float* norm_w  = (const float*)d_in[16];
    const float* fnorm_w = (const float*)d_in[17];
    const float* bb_w    = (const float*)d_in[18];
    const float* bb_b    = (const float*)d_in[19];
    const float* head_w  = (const float*)d_in[20];
    const float* head_b  = (const float*)d_in[21];
    float* out = (float*)d_out;

    float *uraw, *zg, *dbc, *e;
    __nv_bfloat16 *rh, *rl, *ah, *al, *uh, *ul, *wih, *wil, *wxh, *wxl, *woh, *wol;
    cudaGetSymbolAddress((void**)&uraw, g_uraw);
    cudaGetSymbolAddress((void**)&zg,  g_zg);
    cudaGetSymbolAddress((void**)&dbc, g_dbc);
    cudaGetSymbolAddress((void**)&e,   g_e);
    cudaGetSymbolAddress((void**)&rh,  g_rh);
    cudaGetSymbolAddress((void**)&rl,  g_rl);
    cudaGetSymbolAddress((void**)&ah,  g_ah);
    cudaGetSymbolAddress((void**)&al,  g_al);
    cudaGetSymbolAddress((void**)&uh,  g_uh);
    cudaGetSymbolAddress((void**)&ul,  g_ul);
    cudaGetSymbolAddress((void**)&wih, g_wih);
    cudaGetSymbolAddress((void**)&wil, g_wil);
    cudaGetSymbolAddress((void**)&wxh, g_wxh);
    cudaGetSymbolAddress((void**)&wxl, g_wxl);
    cudaGetSymbolAddress((void**)&woh, g_woh);
    cudaGetSymbolAddress((void**)&wol, g_wol);

    const int SMEM128 = 2 * (20480 + 2 * 128 * GP);   // 81920
    const int SMEM64  = 2 * (20480 + 2 * 64 * GP);    // 61440
    cudaFuncSetAttribute(mma_gemm<128, 2>, cudaFuncAttributeMaxDynamicSharedMemorySize, SMEM128);
    cudaFuncSetAttribute(mma_gemm<128, 3>, cudaFuncAttributeMaxDynamicSharedMemorySize, SMEM128);
    cudaFuncSetAttribute(mma_gemm<64,  0>, cudaFuncAttributeMaxDynamicSharedMemorySize, SMEM64);

    // weight conversion (all layers per type)
    wconv_kernel<<<dim3((2 * DI * DM + 255) / 256, NL), 256>>>(in_w, wih, wil, DM, 2 * DI, 2 * DI);
    wconv_kernel<<<dim3((64 * DI + 255) / 256, NL), 256>>>(xproj_w, wxh, wxl, DI, XPJ, 64);
    wconv_kernel<<<dim3((DM * DI + 255) / 256, NL), 256>>>(out_w, woh, wol, DI, DM, DM);

    front_kernel<<<BATCH * KSEQ, PD>>>(x, proj_w, proj_b, ln_w, ln_b);
    patch_kernel<<<dim3(NSEQ, MSEQ), DM>>>(patch_w, patch_b, norm_w);   // layer-0 rms fused

    for (int l = 0; l < NL; l++) {
        // uz = rms(e) @ in_w[l]; split epilogue -> u_raw + silu(z)
        mma_gemm<128, 2><<<dim3(4, NTOK / 128), 256, SMEM128>>>(
            rh, rl, DM, wih + (size_t)l * 2 * DI * DM, wil + (size_t)l * 2 * DI * DM, DM,
            uraw, 0, zg, nullptr, nullptr, nullptr, 2 * DI, DM);
        conv_kernel<<<MSEQ, DI>>>(conv_w + (size_t)l * DI * DC, conv_b + (size_t)l * DI);
        // dbc = u @ xproj_w[l]
        mma_gemm<64, 0><<<dim3(1, NTOK / 128), 256, SMEM64>>>(
            uh, ul, DI, wxh + (size_t)l * 64 * DI, wxl + (size_t)l * 64 * DI, DI,
            dbc, XPJ, nullptr, nullptr, nullptr, nullptr, XPJ, DI);
        scan_kernel<<<MSEQ, DI>>>(dt_w + (size_t)l * DTR * DI, dt_b + (size_t)l * DI,
                                  A_log + (size_t)l * DI * DS, Dp + (size_t)l * DI);
        // e += y @ out_w[l]; fused rms for next layer -> rh/rl
        const float* nwn = norm_w + ((l + 1) % NL) * DM;
        mma_gemm<128, 3><<<dim3(1, NTOK / 128), 256, SMEM128>>>(
            ah, al, DI, woh + (size_t)l * DM * DI, wol + (size_t)l * DM * DI, DI,
            e, DM, nullptr, rh, rl, nwn, DM, DI);
    }

    bb_kernel<<<MSEQ, DM>>>(fnorm_w, bb_w, bb_b);
    head_kernel<<<1, 64>>>(head_w, head_b, out);
}

// round 7
// speedup vs baseline: 1.0652x; 1.0652x over previous
#include <cuda_runtime.h>
#include <cuda_bf16.h>
#include <cstdint>

// ---------------- problem constants ----------------
#define DIN 32
#define KSEQ 512
#define PD 64
#define DM 128
#define NL 4
#define PL 8
#define STR 4
#define DI 256          // 2*DM
#define DS 16
#define DC 4
#define DTR 8
#define NSEQ 127        // (KSEQ-PL)/STR + 1
#define BATCH 32
#define MSEQ (BATCH*PD)         // 2048 sequences
#define NTOK (MSEQ*NSEQ)        // 260096 tokens
#define XPJ (DTR + 2*DS)        // 40

// ---------------- scratch (device globals) ----------------
__device__ float g_h   [BATCH*KSEQ*PD];
__device__ float g_e   [NTOK*DM];           // residual
__device__ float g_uraw[NTOK*DI];           // in-proj u half (raw fp32, pre-conv)
__device__ float g_zg  [NTOK*DI];           // silu(z) gate (fp32)
__device__ float g_dbc [NTOK*XPJ];
__device__ float g_y1  [MSEQ];
// bf16 hi/lo operand buffers
__device__ __nv_bfloat16 g_rh[NTOK*DM];     // rms-normed residual (in-proj A)
__device__ __nv_bfloat16 g_rl[NTOK*DM];
__device__ __nv_bfloat16 g_ah[NTOK*DI];     // gated scan out (out-proj A)
__device__ __nv_bfloat16 g_al[NTOK*DI];
// transposed hi/lo weights [n][k]
__device__ __nv_bfloat16 g_wih[NL*2*DI*DM];
__device__ __nv_bfloat16 g_wil[NL*2*DI*DM];
__device__ __nv_bfloat16 g_wxh[NL*64*DI];
__device__ __nv_bfloat16 g_wxl[NL*64*DI];
__device__ __nv_bfloat16 g_woh[NL*DM*DI];
__device__ __nv_bfloat16 g_wol[NL*DM*DI];

// ---------------- fast transcendentals ----------
__device__ __forceinline__ float frcp_fast(float a) {
    float r;
    asm("rcp.approx.f32 %0, %1;" : "=f"(r) : "f"(a));
    return r;
}
__device__ __forceinline__ float fexp(float x) {     // used in setup paths only
    x = fminf(fmaxf(x, -87.0f), 87.0f);
    return __expf(x);
}
__device__ __forceinline__ float fsilu(float x) {
    return x * frcp_fast(1.0f + __expf(-x));
}

__device__ __forceinline__ float block_reduce_128(float v, float* red) {
    #pragma unroll
    for (int o = 16; o > 0; o >>= 1) v += __shfl_xor_sync(0xffffffffu, v, o);
    int w = threadIdx.x >> 5;
    __syncthreads();
    if ((threadIdx.x & 31) == 0) red[w] = v;
    __syncthreads();
    return red[0] + red[1] + red[2] + red[3];
}

// ---------------- MMA helpers ----------
__device__ __forceinline__ uint32_t smem_u32(const void* p) {
    uint32_t a;
    asm("{ .reg .u64 t; cvta.to.shared.u64 t, %1; cvt.u32.u64 %0, t; }" : "=r"(a) : "l"(p));
    return a;
}
__device__ __forceinline__ void ldm4(uint32_t* r, uint32_t addr) {
    asm volatile("ldmatrix.sync.aligned.m8n8.x4.shared.b16 {%0,%1,%2,%3}, [%4];"
                 : "=r"(r[0]), "=r"(r[1]), "=r"(r[2]), "=r"(r[3]) : "r"(addr));
}
__device__ __forceinline__ void mma16816(float* c, const uint32_t* a, const uint32_t* b) {
    asm volatile(
        "mma.sync.aligned.m16n8k16.row.col.f32.bf16.bf16.f32 "
        "{%0,%1,%2,%3}, {%4,%5,%6,%7}, {%8,%9}, {%0,%1,%2,%3};"
        : "+f"(c[0]), "+f"(c[1]), "+f"(c[2]), "+f"(c[3])
        : "r"(a[0]), "r"(a[1]), "r"(a[2]), "r"(a[3]), "r"(b[0]), "r"(b[1]));
}
__device__ __forceinline__ void cp16(uint32_t dst, const void* src) {
    asm volatile("cp.async.cg.shared.global [%0], [%1], 16;" :: "r"(dst), "l"(src));
}
__device__ __forceinline__ void cp_commit() { asm volatile("cp.async.commit_group;"); }

__device__ __forceinline__ uint32_t pack_hi2(float x, float y) {
    __nv_bfloat16 hx = __float2bfloat16(x), hy = __float2bfloat16(y);
    return (uint32_t)__bfloat16_as_ushort(hx) | ((uint32_t)__bfloat16_as_ushort(hy) << 16);
}
__device__ __forceinline__ uint32_t pack_lo2(float x, float y, uint32_t hi) {
    float hx = __bfloat162float(__ushort_as_bfloat16((unsigned short)(hi & 0xFFFF)));
    float hy = __bfloat162float(__ushort_as_bfloat16((unsigned short)(hi >> 16)));
    __nv_bfloat16 lx = __float2bfloat16(x - hx), ly = __float2bfloat16(y - hy);
    return (uint32_t)__bfloat16_as_ushort(lx) | ((uint32_t)__bfloat16_as_ushort(ly) << 16);
}

// ---------------- double-buffered bf16 hi/lo tensor-core GEMM ----------------
// MODE 0: C[M,Nvalid] = A@B^T (masked store)
// MODE 2: split in-proj: cols<DI -> C (raw fp32), cols>=DI -> silu -> C2
// MODE 3: C += A@B^T (residual e), then fused RMS -> Eh/El with nw
// MODE 4: like MODE 0, but A is computed inline: silu(causal_conv4(g_uraw)) hi/lo
#define GP 80    // smem row pitch bytes (40 bf16; conflict-free ldmatrix)
template<int NTILE, int MODE>
__global__ void __launch_bounds__(256, 2) mma_gemm(
    const __nv_bfloat16* __restrict__ Ah, const __nv_bfloat16* __restrict__ Al, int lda,
    const __nv_bfloat16* __restrict__ Bh, const __nv_bfloat16* __restrict__ Bl, int ldb,
    float* __restrict__ C, int ldc, float* __restrict__ C2,
    __nv_bfloat16* __restrict__ Eh, __nv_bfloat16* __restrict__ El,
    const float* __restrict__ nw, const float* __restrict__ cw, const float* __restrict__ cb,
    int Nvalid, int K)
{
    constexpr int WARP_N = NTILE / 2;
    constexpr int NT8    = WARP_N / 8;
    constexpr int ASZ    = 2 * 128 * GP;
    constexpr int SS     = ASZ + 2 * NTILE * GP;
    extern __shared__ char smem[];
    const uint32_t sb = smem_u32(smem);
    const int tid  = threadIdx.x;
    const int wid  = tid >> 5, lane = tid & 31;
    const int row0 = blockIdx.y * 128;
    const int col0 = blockIdx.x * NTILE;
    const int m_off = (wid & 3) * 32;
    const int n_off = (wid >> 2) * WARP_N;

    const int j = lane >> 3, r = lane & 7;
    const int a_loff = ((j & 1) * 8 + r) * GP + (j >> 1) * 16;
    const int b_loff = ((j >> 1) * 8 + r) * GP + (j & 1) * 16;

    float acc[2][NT8][4];
    #pragma unroll
    for (int mt = 0; mt < 2; mt++)
        #pragma unroll
        for (int nt = 0; nt < NT8; nt++)
            #pragma unroll
            for (int i = 0; i < 4; i++) acc[mt][nt][i] = 0.f;

    auto stage = [&](int st, int k0) {
        uint32_t base = sb + st * SS;
        if (MODE != 4) {
            #pragma unroll
            for (int i = 0; i < 4; i++) {
                int idx = tid + i * 256;
                int h = idx >> 9, rr = (idx >> 2) & 127, c = idx & 3;
                const __nv_bfloat16* src = (h ? Al : Ah) + (size_t)(row0 + rr) * lda + k0 + c * 8;
                cp16(base + h * (128 * GP) + rr * GP + c * 16, src);
            }
        }
        #pragma unroll
        for (int i = 0; i < NTILE / 32; i++) {
            int idx = tid + i * 256;
            int h = idx >= NTILE * 4;
            int id2 = idx & (NTILE * 4 - 1);
            int n = id2 >> 2, c = id2 & 3;
            const __nv_bfloat16* src = (h ? Bl : Bh) + (size_t)(col0 + n) * ldb + k0 + c * 8;
            cp16(base + ASZ + h * (NTILE * GP) + n * GP + c * 16, src);
        }
        cp_commit();
    };

    // MODE 4: compute A chunk (128 tokens x 32 ch) = silu(conv(uraw)) hi/lo
    auto convA = [&](int st, int k0) {
        uint32_t base = sb + st * SS;
        #pragma unroll
        for (int i = 0; i < 2; i++) {
            int idx = tid + i * 256;            // 512 slots
            int rr = idx >> 2, c = idx & 3;
            int tok = row0 + rr;
            int mm = tok / NSEQ;
            int n  = tok - mm * NSEQ;
            int ch0 = k0 + c * 8;
            const float* up = g_uraw + (size_t)tok * DI + ch0;
            float t0[8], t1[8] = {0}, t2[8] = {0}, t3[8] = {0};
            *(float4*)(t0)     = *(const float4*)(up);
            *(float4*)(t0 + 4) = *(const float4*)(up + 4);
            if (n >= 1) { *(float4*)(t1) = *(const float4*)(up - DI);
                          *(float4*)(t1 + 4) = *(const float4*)(up - DI + 4); }
            if (n >= 2) { *(float4*)(t2) = *(const float4*)(up - 2 * DI);
                          *(float4*)(t2 + 4) = *(const float4*)(up - 2 * DI + 4); }
            if (n >= 3) { *(float4*)(t3) = *(const float4*)(up - 3 * DI);
                          *(float4*)(t3 + 4) = *(const float4*)(up - 3 * DI + 4); }
            float bias[8];
            *(float4*)(bias)     = *(const float4*)(cb + ch0);
            *(float4*)(bias + 4) = *(const float4*)(cb + ch0 + 4);
            float u[8];
            #pragma unroll
            for (int ch = 0; ch < 8; ch++) {
                float4 w = *(const float4*)(cw + (ch0 + ch) * DC);
                float uc = bias[ch];
                uc = fmaf(t3[ch], w.x, uc);     // x(t-3) * w0
                uc = fmaf(t2[ch], w.y, uc);
                uc = fmaf(t1[ch], w.z, uc);
                uc = fmaf(t0[ch], w.w, uc);
                u[ch] = fsilu(uc);
            }
            uint2 hv, lv;
            hv.x = pack_hi2(u[0], u[1]); lv.x = pack_lo2(u[0], u[1], hv.x);
            hv.y = pack_hi2(u[2], u[3]); lv.y = pack_lo2(u[2], u[3], hv.y);
            *(uint2*)(smem + (base - sb) + rr * GP + c * 16) = hv;
            uint2 hv2, lv2;
            hv2.x = pack_hi2(u[4], u[5]); lv2.x = pack_lo2(u[4], u[5], hv2.x);
            hv2.y = pack_hi2(u[6], u[7]); lv2.y = pack_lo2(u[6], u[7], hv2.y);
            // contiguous 8 ch = 16B; c*16 covers ch 8c..8c+7 -> two uint2 writes
            *(uint2*)(smem + (base - sb) + rr * GP + c * 16 + 8) = hv2;
            *(uint2*)(smem + (base - sb) + 128 * GP + rr * GP + c * 16)     = lv;
            *(uint2*)(smem + (base - sb) + 128 * GP + rr * GP + c * 16 + 8) = lv2;
        }
    };

    auto compute = [&](int i) {
        uint32_t base = sb + (i & 1) * SS;
        uint32_t sA[2] = { base, base + 128 * GP };
        uint32_t sB[2] = { base + ASZ, base + ASZ + NTILE * GP };
        #pragma unroll
        for (int kk = 0; kk < 32; kk += 16) {
            uint32_t afr[2][2][4];
            #pragma unroll
            for (int mt = 0; mt < 2; mt++)
                #pragma unroll
                for (int h = 0; h < 2; h++)
                    ldm4(afr[mt][h], sA[h] + (m_off + mt * 16) * GP + kk * 2 + a_loff);
            uint32_t bfr[NTILE / 32][2][4];
            #pragma unroll
            for (int np = 0; np < NTILE / 32; np++)
                #pragma unroll
                for (int h = 0; h < 2; h++)
                    ldm4(bfr[np][h], sB[h] + (n_off + np * 16) * GP + kk * 2 + b_loff);
            #pragma unroll
            for (int mt = 0; mt < 2; mt++)
                #pragma unroll
                for (int nt = 0; nt < NT8; nt++) {
                    const uint32_t* bh = &bfr[nt >> 1][0][(nt & 1) * 2];
                    const uint32_t* bl = &bfr[nt >> 1][1][(nt & 1) * 2];
                    mma16816(acc[mt][nt], afr[mt][0], bh);
                    mma16816(acc[mt][nt], afr[mt][0], bl);
                    mma16816(acc[mt][nt], afr[mt][1], bh);
                }
        }
    };

    const int nk = K / 32;
    stage(0, 0);
    for (int i = 0; i < nk; i++) {
        if (i + 1 < nk) {
            stage((i + 1) & 1, (i + 1) * 32);
            asm volatile("cp.async.wait_group 1;" ::: "memory");
        } else {
            asm volatile("cp.async.wait_group 0;" ::: "memory");
        }
        if (MODE == 4) convA(i & 1, i * 32);
        __syncthreads();
        compute(i);
        __syncthreads();
    }

    const int lr = lane >> 2, lq = lane & 3;
    if (MODE == 0 || MODE == 4) {
        #pragma unroll
        for (int mt = 0; mt < 2; mt++)
            #pragma unroll
            for (int nt = 0; nt < NT8; nt++) {
                int rbase = row0 + m_off + mt * 16 + lr;
                int cc = col0 + n_off + nt * 8 + lq * 2;
                if (cc < Nvalid) {
                    *(float2*)(C + (size_t)rbase * ldc + cc) =
                        make_float2(acc[mt][nt][0], acc[mt][nt][1]);
                    *(float2*)(C + (size_t)(rbase + 8) * ldc + cc) =
                        make_float2(acc[mt][nt][2], acc[mt][nt][3]);
                }
            }
    } else if (MODE == 2) {
        #pragma unroll
        for (int mt = 0; mt < 2; mt++)
            #pragma unroll
            for (int nt = 0; nt < NT8; nt++) {
                int rbase = row0 + m_off + mt * 16 + lr;
                int cc = col0 + n_off + nt * 8 + lq * 2;
                if (cc < DI) {
                    *(float2*)(C + (size_t)rbase * DI + cc) =
                        make_float2(acc[mt][nt][0], acc[mt][nt][1]);
                    *(float2*)(C + (size_t)(rbase + 8) * DI + cc) =
                        make_float2(acc[mt][nt][2], acc[mt][nt][3]);
                } else {
                    int cz = cc - DI;
                    *(float2*)(C2 + (size_t)rbase * DI + cz) =
                        make_float2(fsilu(acc[mt][nt][0]), fsilu(acc[mt][nt][1]));
                    *(float2*)(C2 + (size_t)(rbase + 8) * DI + cz) =
                        make_float2(fsilu(acc[mt][nt][2]), fsilu(acc[mt][nt][3]));
                }
            }
    } else {  // MODE 3
        float* ssq = (float*)smem;
        const int half = wid >> 2;
        float part[4] = {0.f, 0.f, 0.f, 0.f};
        #pragma unroll
        for (int mt = 0; mt < 2; mt++)
            #pragma unroll
            for (int nt = 0; nt < NT8; nt++) {
                int r0g = row0 + m_off + mt * 16 + lr;
                int cc = n_off + nt * 8 + lq * 2;
                float2* p0 = (float2*)(C + (size_t)r0g * ldc + cc);
                float2* p1 = (float2*)(C + (size_t)(r0g + 8) * ldc + cc);
                float2 o0 = *p0, o1 = *p1;
                o0.x += acc[mt][nt][0]; o0.y += acc[mt][nt][1];
                o1.x += acc[mt][nt][2]; o1.y += acc[mt][nt][3];
                *p0 = o0; *p1 = o1;
                acc[mt][nt][0] = o0.x; acc[mt][nt][1] = o0.y;
                acc[mt][nt][2] = o1.x; acc[mt][nt][3] = o1.y;
                part[mt * 2 + 0] += o0.x * o0.x + o0.y * o0.y;
                part[mt * 2 + 1] += o1.x * o1.x + o1.y * o1.y;
            }
        #pragma unroll
        for (int s = 0; s < 4; s++) {
            part[s] += __shfl_xor_sync(0xffffffffu, part[s], 1);
            part[s] += __shfl_xor_sync(0xffffffffu, part[s], 2);
        }
        if (lq == 0) {
            ssq[half * 128 + m_off + lr]      = part[0];
            ssq[half * 128 + m_off + lr + 8]  = part[1];
            ssq[half * 128 + m_off + lr + 16] = part[2];
            ssq[half * 128 + m_off + lr + 24] = part[3];
        }
        __syncthreads();
        #pragma unroll
        for (int mt = 0; mt < 2; mt++) {
            int rr = m_off + mt * 16 + lr;
            float sc0 = rsqrtf((ssq[rr]     + ssq[128 + rr])     * (1.0f / DM) + 1e-5f);
            float sc1 = rsqrtf((ssq[rr + 8] + ssq[128 + rr + 8]) * (1.0f / DM) + 1e-5f);
            int r0g = row0 + rr;
            #pragma unroll
            for (int nt = 0; nt < NT8; nt++) {
                int cc = n_off + nt * 8 + lq * 2;
                float w0 = nw[cc], w1 = nw[cc + 1];
                float a0 = acc[mt][nt][0] * sc0 * w0, a1 = acc[mt][nt][1] * sc0 * w1;
                float a2 = acc[mt][nt][2] * sc1 * w0, a3 = acc[mt][nt][3] * sc1 * w1;
                uint32_t h0 = pack_hi2(a0, a1), l0 = pack_lo2(a0, a1, h0);
                uint32_t h1 = pack_hi2(a2, a3), l1 = pack_lo2(a2, a3, h1);
                *(uint32_t*)(Eh + (size_t)r0g * DM + cc)       = h0;
                *(uint32_t*)(El + (size_t)r0g * DM + cc)       = l0;
                *(uint32_t*)(Eh + (size_t)(r0g + 8) * DM + cc) = h1;
                *(uint32_t*)(El + (size_t)(r0g + 8) * DM + cc) = l1;
            }
        }
    }
}

// ---------------- weight convert+transpose ----------
__global__ void wconv_kernel(const float* __restrict__ src, __nv_bfloat16* __restrict__ dh,
                             __nv_bfloat16* __restrict__ dl, int K, int Nsrc, int Npad) {
    int l = blockIdx.y;
    src += (size_t)l * K * Nsrc;
    dh  += (size_t)l * Npad * K;
    dl  += (size_t)l * Npad * K;
    int idx = blockIdx.x * 256 + threadIdx.x;
    if (idx >= Npad * K) return;
    int n = idx / K, k = idx - n * K;
    float v = (n < Nsrc) ? src[(size_t)k * Nsrc + n] : 0.f;
    __nv_bfloat16 h = __float2bfloat16(v);
    dh[idx] = h;
    dl[idx] = __float2bfloat16(v - __bfloat162float(h));
}

// ---------------- 1) front ----------------
__global__ void front_kernel(const float* __restrict__ x,  const float* __restrict__ pw,
                             const float* __restrict__ pb, const float* __restrict__ lw,
                             const float* __restrict__ lb) {
    int row = blockIdx.x;
    int pd  = threadIdx.x;         // 64
    __shared__ float xr[DIN];
    __shared__ float red[2];
    if (pd < DIN) xr[pd] = x[row * DIN + pd];
    __syncthreads();
    float acc = pb[pd];
    #pragma unroll
    for (int i = 0; i < DIN; i++) acc = fmaf(xr[i], pw[i * PD + pd], acc);
    float s = acc;
    #pragma unroll
    for (int o = 16; o > 0; o >>= 1) s += __shfl_xor_sync(0xffffffffu, s, o);
    if ((pd & 31) == 0) red[pd >> 5] = s;
    __syncthreads();
    float mu = (red[0] + red[1]) * (1.0f / PD);
    __syncthreads();
    float d = acc - mu;
    float q = d * d;
    #pragma unroll
    for (int o = 16; o > 0; o >>= 1) q += __shfl_xor_sync(0xffffffffu, q, o);
    if ((pd & 31) == 0) red[pd >> 5] = q;
    __syncthreads();
    float var = (red[0] + red[1]) * (1.0f / PD);
    g_h[row * PD + pd] = d * rsqrtf(var + 1e-5f) * lw[pd] + lb[pd];
}

// ---------------- 2) patch embed + fused layer-0 RMS ----------------
__global__ void patch_kernel(const float* __restrict__ patch_w, const float* __restrict__ patch_b,
                             const float* __restrict__ nw0) {
    int n  = blockIdx.x;
    int m  = blockIdx.y;
    int dm = threadIdx.x;          // 128
    int b  = m >> 6, pd = m & 63;
    __shared__ float hv[PL];
    __shared__ float red[4];
    if (dm < PL) hv[dm] = g_h[(b * KSEQ + n * STR + dm) * PD + pd];
    __syncthreads();
    float acc = patch_b[dm];
    #pragma unroll
    for (int pl = 0; pl < PL; pl++) acc = fmaf(hv[pl], patch_w[pl * DM + dm], acc);
    size_t tok = (size_t)m * NSEQ + n;
    g_e[tok * DM + dm] = acc;
    float ss = block_reduce_128(acc * acc, red);
    float sc = rsqrtf(ss * (1.0f / DM) + 1e-5f);
    float a = acc * sc * nw0[dm];
    __nv_bfloat16 h = __float2bfloat16(a);
    g_rh[tok * DM + dm] = h;
    g_rl[tok * DM + dm] = __float2bfloat16(a - __bfloat162float(h));
}

// ---------------- 5) fused conv + dt-proj + softplus + scan + gate ----------
__global__ void scan_kernel(const float* __restrict__ dtw, const float* __restrict__ dtbp,
                            const float* __restrict__ alog, const float* __restrict__ dpp,
                            const float* __restrict__ cw, const float* __restrict__ cb) {
    int m = blockIdx.x;            // MSEQ
    int d = threadIdx.x;           // DI
    __shared__ float buf[2][8][XPJ];
    float wreg[DTR];
    #pragma unroll
    for (int i = 0; i < DTR; i++) wreg[i] = dtw[i * DI + d];
    float dtb = dtbp[d];
    float Dpv = dpp[d];
    float cw0 = cw[d * DC + 0], cw1 = cw[d * DC + 1], cw2 = cw[d * DC + 2], cw3 = cw[d * DC + 3];
    float cbv = cb[d];
    bool fast = true;
    #pragma unroll
    for (int s = 0; s < DS; s++) {
        float as = -fexp(alog[d * DS + s]);
        fast = fast && (fabsf(as + (float)(s + 1)) < 1e-3f);
    }
    float hst[DS];
    #pragma unroll
    for (int s = 0; s < DS; s++) hst[s] = 0.f;
    float x0 = 0.f, x1 = 0.f, x2 = 0.f;     // conv taps

    const float* dbc = g_dbc + (size_t)m * NSEQ * XPJ;
    for (int idx = d; idx < 8 * XPJ; idx += DI)
        buf[0][idx / XPJ][idx % XPJ] = dbc[idx];
    __syncthreads();

    const int NTILES = (NSEQ + 7) / 8;   // 16
    for (int jt = 0; jt < NTILES; jt++) {
        int t0 = jt * 8;
        int cnt = min(8, NSEQ - t0);
        if (jt + 1 < NTILES) {
            int t1 = t0 + 8;
            int cnt1 = min(8, NSEQ - t1);
            for (int idx = d; idx < cnt1 * XPJ; idx += DI)
                buf[(jt + 1) & 1][idx / XPJ][idx % XPJ] = dbc[(size_t)t1 * XPJ + idx];
        }
        const float* bj = &buf[jt & 1][0][0];
        for (int tt = 0; tt < cnt; tt++) {
            int t = t0 + tt;
            const float* s40 = bj + tt * XPJ;
            size_t off = ((size_t)m * NSEQ + t) * DI + d;
            // inline conv + silu
            float xt = g_uraw[off];
            float uc = cbv;
            uc = fmaf(x0, cw0, uc);
            uc = fmaf(x1, cw1, uc);
            uc = fmaf(x2, cw2, uc);
            uc = fmaf(xt, cw3, uc);
            x0 = x1; x1 = x2; x2 = xt;
            float u_td = uc * frcp_fast(1.0f + __expf(-uc));
            // dt-proj + softplus
            float v = dtb;
            #pragma unroll
            for (int i = 0; i < DTR; i++) v = fmaf(s40[i], wreg[i], v);
            float e1 = __expf(v);
            float delta = (v > 20.f) ? v : __logf(1.0f + e1);
            float du = delta * u_td;
            float y;
            if (fast) {
                float rr = frcp_fast(1.0f + e1);     // exp(-softplus(v))
                float pw[DS];
                pw[0] = rr;
                #pragma unroll
                for (int s = 1; s < DS; s++) pw[s] = pw[s >> 1] * pw[(s - 1) >> 1];
                float y0 = 0.f, y1 = 0.f, y2 = 0.f, y3 = 0.f;
                #pragma unroll
                for (int s = 0; s < DS; s += 4) {
                    hst[s]     = fmaf(pw[s],     hst[s],     du * s40[DTR + s]);
                    hst[s + 1] = fmaf(pw[s + 1], hst[s + 1], du * s40[DTR + s + 1]);
                    hst[s + 2] = fmaf(pw[s + 2], hst[s + 2], du * s40[DTR + s + 2]);
                    hst[s + 3] = fmaf(pw[s + 3], hst[s + 3], du * s40[DTR + s + 3]);
                    y0 = fmaf(hst[s],     s40[DTR + DS + s],     y0);
                    y1 = fmaf(hst[s + 1], s40[DTR + DS + s + 1], y1);
                    y2 = fmaf(hst[s + 2], s40[DTR + DS + s + 2], y2);
                    y3 = fmaf(hst[s + 3], s40[DTR + DS + s + 3], y3);
                }
                y = (y0 + y1) + (y2 + y3);
            } else {
                y = 0.f;
                #pragma unroll
                for (int s = 0; s < DS; s++) {
                    float as = -fexp(alog[d * DS + s]);
                    float dA = fexp(delta * as);
                    hst[s] = fmaf(dA, hst[s], du * s40[DTR + s]);
                    y = fmaf(hst[s], s40[DTR + DS + s], y);
                }
            }
            float yo = fmaf(u_td, Dpv, y);
            float yg = yo * g_zg[off];
            __nv_bfloat16 h = __float2bfloat16(yg);
            g_ah[off] = h;
            g_al[off] = __float2bfloat16(yg - __bfloat162float(h));
        }
        __syncthreads();
    }
}

// ---------------- 6) final RMS + bb dot (warp-per-token) ----------------
__global__ void bb_kernel(const float* __restrict__ fnw, const float* __restrict__ bbw,
                          const float* __restrict__ bbb) {
    int m = blockIdx.x;
    int tid = threadIdx.x;         // 128
    int w = tid >> 5, lane = tid & 31;
    __shared__ float red[4];
    float4 fw = *(const float4*)(fnw + lane * 4);
    float acc0 = 0.f, acc1 = 0.f, acc2 = 0.f, acc3 = 0.f;
    for (int n = w; n < NSEQ; n += 4) {
        const float* er = g_e + ((size_t)m * NSEQ + n) * DM;
        float4 v = *(const float4*)(er + lane * 4);
        float ss = v.x * v.x + v.y * v.y + v.z * v.z + v.w * v.w;
        #pragma unroll
        for (int o = 16; o > 0; o >>= 1) ss += __shfl_xor_sync(0xffffffffu, ss, o);
        float sc = rsqrtf(ss * (1.0f / DM) + 1e-5f);
        float4 bw = *(const float4*)(bbw + n * DM + lane * 4);
        acc0 = fmaf(v.x * sc * fw.x, bw.x, acc0);
        acc1 = fmaf(v.y * sc * fw.y, bw.y, acc1);
        acc2 = fmaf(v.z * sc * fw.z, bw.z, acc2);
        acc3 = fmaf(v.w * sc * fw.w, bw.w, acc3);
    }
    float tot = acc0 + acc1 + acc2 + acc3;
    #pragma unroll
    for (int o = 16; o > 0; o >>= 1) tot += __shfl_xor_sync(0xffffffffu, tot, o);
    if (lane == 0) red[w] = tot;
    __syncthreads();
    if (tid == 0) g_y1[m] = red[0] + red[1] + red[2] + red[3] + bbb[0];
}

// ---------------- 7) head ----------------
__global__ void head_kernel(const float* __restrict__ hw, const float* __restrict__ hb,
                            float* __restrict__ out) {
    int t = threadIdx.x;           // 64
    int b = t >> 1, jj = t & 1;
    float acc = hb[jj];
    #pragma unroll
    for (int p = 0; p < PD; p++) acc = fmaf(g_y1[b * PD + p], hw[p * 2 + jj], acc);
    out[b * 2 + jj] = acc;
}

// ---------------- launch ----------------
extern "C" void kernel_launch(void* const* d_in, const int* in_sizes, int n_in,
                              void* d_out, int out_size) {
    const float* x       = (const float*)d_in[0];
    const float* proj_w  = (const float*)d_in[1];
    const float* proj_b  = (const float*)d_in[2];
    const float* ln_w    = (const float*)d_in[3];
    const float* ln_b    = (const float*)d_in[4];
    const float* patch_w = (const float*)d_in[5];
    const float* patch_b = (const float*)d_in[6];
    const float* in_w    = (const float*)d_in[7];
    const float* conv_w  = (const float*)d_in[8];
    const float* conv_b  = (const float*)d_in[9];
    const float* xproj_w = (const float*)d_in[10];
    const float* dt_w    = (const float*)d_in[11];
    const float* dt_b    = (const float*)d_in[12];
    const float* A_log   = (const float*)d_in[13];
    const float* Dp      = (const float*)d_in[14];
    const float* out_w   = (const float*)d_in[15];
    const float* norm_w  = (const float*)d_in[16];
    const float* fnorm_w = (const float*)d_in[17];
    const float* bb_w    = (const float*)d_in[18];
    const float* bb_b    = (const float*)d_in[19];
    const float* head_w  = (const float*)d_in[20];
    const float* head_b  = (const float*)d_in[21];
    float* out = (float*)d_out;

    float *uraw, *zg, *dbc, *e;
    __nv_bfloat16 *rh, *rl, *ah, *al, *wih, *wil, *wxh, *wxl, *woh, *wol;
    cudaGetSymbolAddress((void**)&uraw, g_uraw);
    cudaGetSymbolAddress((void**)&zg,  g_zg);
    cudaGetSymbolAddress((void**)&dbc, g_dbc);
    cudaGetSymbolAddress((void**)&e,   g_e);
    cudaGetSymbolAddress((void**)&rh,  g_rh);
    cudaGetSymbolAddress((void**)&rl,  g_rl);
    cudaGetSymbolAddress((void**)&ah,  g_ah);
    cudaGetSymbolAddress((void**)&al,  g_al);
    cudaGetSymbolAddress((void**)&wih, g_wih);
    cudaGetSymbolAddress((void**)&wil, g_wil);
    cudaGetSymbolAddress((void**)&wxh, g_wxh);
    cudaGetSymbolAddress((void**)&wxl, g_wxl);
    cudaGetSymbolAddress((void**)&woh, g_woh);
    cudaGetSymbolAddress((void**)&wol, g_wol);

    const int SMEM128 = 2 * (20480 + 2 * 128 * GP);   // 81920
    const int SMEM64  = 2 * (20480 + 2 * 64 * GP);    // 61440
    cudaFuncSetAttribute(mma_gemm<128, 2>, cudaFuncAttributeMaxDynamicSharedMemorySize, SMEM128);
    cudaFuncSetAttribute(mma_gemm<128, 3>, cudaFuncAttributeMaxDynamicSharedMemorySize, SMEM128);
    cudaFuncSetAttribute(mma_gemm<64,  4>, cudaFuncAttributeMaxDynamicSharedMemorySize, SMEM64);

    wconv_kernel<<<dim3((2 * DI * DM + 255) / 256, NL), 256>>>(in_w, wih, wil, DM, 2 * DI, 2 * DI);
    wconv_kernel<<<dim3((64 * DI + 255) / 256, NL), 256>>>(xproj_w, wxh, wxl, DI, XPJ, 64);
    wconv_kernel<<<dim3((DM * DI + 255) / 256, NL), 256>>>(out_w, woh, wol, DI, DM, DM);

    front_kernel<<<BATCH * KSEQ, PD>>>(x, proj_w, proj_b, ln_w, ln_b);
    patch_kernel<<<dim3(NSEQ, MSEQ), DM>>>(patch_w, patch_b, norm_w);

    for (int l = 0; l < NL; l++) {
        const float* cwl = conv_w + (size_t)l * DI * DC;
        const float* cbl = conv_b + (size_t)l * DI;
        // uz = rms(e) @ in_w[l]; split epilogue -> u_raw + silu(z)
        mma_gemm<128, 2><<<dim3(4, NTOK / 128), 256, SMEM128>>>(
            rh, rl, DM, wih + (size_t)l * 2 * DI * DM, wil + (size_t)l * 2 * DI * DM, DM,
            uraw, 0, zg, nullptr, nullptr, nullptr, nullptr, nullptr, 2 * DI, DM);
        // dbc = silu(conv(uraw)) @ xproj_w[l]  (conv fused into A-staging)
        mma_gemm<64, 4><<<dim3(1, NTOK / 128), 256, SMEM64>>>(
            nullptr, nullptr, DI, wxh + (size_t)l * 64 * DI, wxl + (size_t)l * 64 * DI, DI,
            dbc, XPJ, nullptr, nullptr, nullptr, nullptr, cwl, cbl, XPJ, DI);
        // scan (conv fused inline)
        scan_kernel<<<MSEQ, DI>>>(dt_w + (size_t)l * DTR * DI, dt_b + (size_t)l * DI,
                                  A_log + (size_t)l * DI * DS, Dp + (size_t)l * DI, cwl, cbl);
        // e += y @ out_w[l]; fused rms for next layer -> rh/rl
        const float* nwn = norm_w + ((l + 1) % NL) * DM;
        mma_gemm<128, 3><<<dim3(1, NTOK / 128), 256, SMEM128>>>(
            ah, al, DI, woh + (size_t)l * DM * DI, wol + (size_t)l * DM * DI, DI,
            e, DM, nullptr, rh, rl, nwn, nullptr, nullptr, DM, DI);
    }

    bb_kernel<<<MSEQ, DM>>>(fnorm_w, bb_w, bb_b);
    head_kernel<<<1, 64>>>(head_w, head_b, out);
}

// round 8
// speedup vs baseline: 1.3693x; 1.2855x over previous
#include <cuda_runtime.h>
#include <cuda_bf16.h>
#include <cstdint>

// ---------------- problem constants ----------------
#define DIN 32
#define KSEQ 512
#define PD 64
#define DM 128
#define NL 4
#define PL 8
#define STR 4
#define DI 256          // 2*DM
#define DS 16
#define DC 4
#define DTR 8
#define NSEQ 127        // (KSEQ-PL)/STR + 1
#define BATCH 32
#define MSEQ (BATCH*PD)         // 2048 sequences
#define NTOK (MSEQ*NSEQ)        // 260096 tokens
#define XPJ (DTR + 2*DS)        // 40

// ---------------- scratch (device globals) ----------------
__device__ float g_h   [BATCH*KSEQ*PD];
__device__ float g_e   [NTOK*DM];           // residual
__device__ float g_uraw[NTOK*DI];           // in-proj u half (raw fp32, pre-conv)
__device__ float g_zg  [NTOK*DI];           // silu(z) gate (fp32)
__device__ float g_dbc [NTOK*XPJ];
__device__ float g_y1  [MSEQ];
// bf16 hi/lo operand buffers
__device__ __nv_bfloat16 g_rh[NTOK*DM];     // rms-normed residual (in-proj A)
__device__ __nv_bfloat16 g_rl[NTOK*DM];
__device__ __nv_bfloat16 g_ah[NTOK*DI];     // gated scan out (out-proj A)
__device__ __nv_bfloat16 g_al[NTOK*DI];
// transposed hi/lo weights [n][k]
__device__ __nv_bfloat16 g_wih[NL*2*DI*DM];
__device__ __nv_bfloat16 g_wil[NL*2*DI*DM];
__device__ __nv_bfloat16 g_wxh[NL*64*DI];
__device__ __nv_bfloat16 g_wxl[NL*64*DI];
__device__ __nv_bfloat16 g_woh[NL*DM*DI];
__device__ __nv_bfloat16 g_wol[NL*DM*DI];

// ---------------- fast transcendentals ----------
__device__ __forceinline__ float frcp_fast(float a) {
    float r;
    asm("rcp.approx.f32 %0, %1;" : "=f"(r) : "f"(a));
    return r;
}
__device__ __forceinline__ float fexp(float x) {
    x = fminf(fmaxf(x, -87.0f), 87.0f);
    return __expf(x);
}
__device__ __forceinline__ float fsilu(float x) {
    return x * frcp_fast(1.0f + __expf(-x));
}

__device__ __forceinline__ float block_reduce_128(float v, float* red) {
    #pragma unroll
    for (int o = 16; o > 0; o >>= 1) v += __shfl_xor_sync(0xffffffffu, v, o);
    int w = threadIdx.x >> 5;
    __syncthreads();
    if ((threadIdx.x & 31) == 0) red[w] = v;
    __syncthreads();
    return red[0] + red[1] + red[2] + red[3];
}

// ---------------- MMA helpers ----------
__device__ __forceinline__ uint32_t smem_u32(const void* p) {
    uint32_t a;
    asm("{ .reg .u64 t; cvta.to.shared.u64 t, %1; cvt.u32.u64 %0, t; }" : "=r"(a) : "l"(p));
    return a;
}
__device__ __forceinline__ void ldm4(uint32_t* r, uint32_t addr) {
    asm volatile("ldmatrix.sync.aligned.m8n8.x4.shared.b16 {%0,%1,%2,%3}, [%4];"
                 : "=r"(r[0]), "=r"(r[1]), "=r"(r[2]), "=r"(r[3]) : "r"(addr));
}
__device__ __forceinline__ void mma16816(float* c, const uint32_t* a, const uint32_t* b) {
    asm volatile(
        "mma.sync.aligned.m16n8k16.row.col.f32.bf16.bf16.f32 "
        "{%0,%1,%2,%3}, {%4,%5,%6,%7}, {%8,%9}, {%0,%1,%2,%3};"
        : "+f"(c[0]), "+f"(c[1]), "+f"(c[2]), "+f"(c[3])
        : "r"(a[0]), "r"(a[1]), "r"(a[2]), "r"(a[3]), "r"(b[0]), "r"(b[1]));
}
__device__ __forceinline__ void cp16(uint32_t dst, const void* src) {
    asm volatile("cp.async.cg.shared.global [%0], [%1], 16;" :: "r"(dst), "l"(src));
}
__device__ __forceinline__ void cp_commit() { asm volatile("cp.async.commit_group;"); }

__device__ __forceinline__ uint32_t pack_hi2(float x, float y) {
    __nv_bfloat16 hx = __float2bfloat16(x), hy = __float2bfloat16(y);
    return (uint32_t)__bfloat16_as_ushort(hx) | ((uint32_t)__bfloat16_as_ushort(hy) << 16);
}
__device__ __forceinline__ uint32_t pack_lo2(float x, float y, uint32_t hi) {
    float hx = __bfloat162float(__ushort_as_bfloat16((unsigned short)(hi & 0xFFFF)));
    float hy = __bfloat162float(__ushort_as_bfloat16((unsigned short)(hi >> 16)));
    __nv_bfloat16 lx = __float2bfloat16(x - hx), ly = __float2bfloat16(y - hy);
    return (uint32_t)__bfloat16_as_ushort(lx) | ((uint32_t)__bfloat16_as_ushort(ly) << 16);
}

#define GP 80    // B smem row pitch bytes (40 bf16; conflict-free ldmatrix)

// ---------------- in-proj GEMM: A-resident, loops all 4 N-tiles ----------------
// U[tok][0..255] = rms(e) @ in_w cols 0..255 ; Z = silu(cols 256..511)
__global__ void __launch_bounds__(256, 2) inproj_gemm(
    const __nv_bfloat16* __restrict__ Ah, const __nv_bfloat16* __restrict__ Al,
    const __nv_bfloat16* __restrict__ Bh, const __nv_bfloat16* __restrict__ Bl,
    float* __restrict__ U, float* __restrict__ Z)
{
    constexpr int AP   = 272;            // A pitch bytes (256 data + 16 pad)
    constexpr int ABUF = 128 * AP;       // 34816 per plane
    constexpr int BOFF = 2 * ABUF;       // 69632
    constexpr int BSTG = 2 * 128 * GP;   // 20480 per stage (hi+lo)
    extern __shared__ char smem[];
    const uint32_t sb = smem_u32(smem);
    const int tid  = threadIdx.x;
    const int wid  = tid >> 5, lane = tid & 31;
    const int row0 = blockIdx.x * 128;
    const int m_off = (wid & 3) * 32;
    const int n_off = (wid >> 2) * 64;

    const int j = lane >> 3, r = lane & 7;
    const int a_loff = ((j & 1) * 8 + r) * AP + (j >> 1) * 16;
    const int b_loff = ((j >> 1) * 8 + r) * GP + (j & 1) * 16;

    // stage full A tile (128 rows x 128 k, hi+lo) = 64KB
    #pragma unroll
    for (int i = 0; i < 16; i++) {
        int idx = tid + i * 256;
        int h = idx >> 11, id2 = idx & 2047;
        int rr = id2 >> 4, c = id2 & 15;
        const __nv_bfloat16* src = (h ? Al : Ah) + (size_t)(row0 + rr) * DM + c * 8;
        cp16(sb + h * ABUF + rr * AP + c * 16, src);
    }
    auto stageB = [&](int st, int ntile, int k0) {
        #pragma unroll
        for (int i = 0; i < 4; i++) {
            int idx = tid + i * 256;
            int h = idx >> 9, id2 = idx & 511;
            int n = id2 >> 2, c = id2 & 3;
            const __nv_bfloat16* src = (h ? Bl : Bh) + (size_t)(ntile * 128 + n) * DM + k0 + c * 8;
            cp16(sb + BOFF + st * BSTG + h * (128 * GP) + n * GP + c * 16, src);
        }
    };

    stageB(0, 0, 0);
    cp_commit();

    float acc[2][8][4];
    #pragma unroll
    for (int mt = 0; mt < 2; mt++)
        #pragma unroll
        for (int f = 0; f < 8; f++)
            #pragma unroll
            for (int i = 0; i < 4; i++) acc[mt][f][i] = 0.f;

    const int lr = lane >> 2, lq = lane & 3;
    int cg = 0;
    for (int ntile = 0; ntile < 4; ntile++) {
        for (int kc = 0; kc < 4; kc++, cg++) {
            if (cg < 15) {
                stageB((cg + 1) & 1, (cg + 1) >> 2, ((cg + 1) & 3) * 32);
                cp_commit();
                asm volatile("cp.async.wait_group 1;" ::: "memory");
            } else {
                asm volatile("cp.async.wait_group 0;" ::: "memory");
            }
            __syncthreads();
            uint32_t bbase = sb + BOFF + (cg & 1) * BSTG;
            uint32_t sB[2] = { bbase, bbase + 128 * GP };
            #pragma unroll
            for (int kk = 0; kk < 32; kk += 16) {
                uint32_t afr[2][2][4];
                #pragma unroll
                for (int mt = 0; mt < 2; mt++)
                    #pragma unroll
                    for (int h = 0; h < 2; h++)
                        ldm4(afr[mt][h], sb + h * ABUF + (m_off + mt * 16) * AP
                                         + (kc * 32 + kk) * 2 + a_loff);
                uint32_t bfr[4][2][4];
                #pragma unroll
                for (int np = 0; np < 4; np++)
                    #pragma unroll
                    for (int h = 0; h < 2; h++)
                        ldm4(bfr[np][h], sB[h] + (n_off + np * 16) * GP + kk * 2 + b_loff);
                #pragma unroll
                for (int mt = 0; mt < 2; mt++)
                    #pragma unroll
                    for (int f = 0; f < 8; f++) {
                        const uint32_t* bh = &bfr[f >> 1][0][(f & 1) * 2];
                        const uint32_t* bl = &bfr[f >> 1][1][(f & 1) * 2];
                        mma16816(acc[mt][f], afr[mt][0], bh);
                        mma16816(acc[mt][f], afr[mt][0], bl);
                        mma16816(acc[mt][f], afr[mt][1], bh);
                    }
            }
            __syncthreads();
        }
        // epilogue for this N-tile, then reset accumulators
        #pragma unroll
        for (int mt = 0; mt < 2; mt++)
            #pragma unroll
            for (int f = 0; f < 8; f++) {
                int rbase = row0 + m_off + mt * 16 + lr;
                int cc = ntile * 128 + n_off + f * 8 + lq * 2;
                if (ntile < 2) {
                    *(float2*)(U + (size_t)rbase * DI + cc) =
                        make_float2(acc[mt][f][0], acc[mt][f][1]);
                    *(float2*)(U + (size_t)(rbase + 8) * DI + cc) =
                        make_float2(acc[mt][f][2], acc[mt][f][3]);
                } else {
                    int cz = cc - DI;
                    *(float2*)(Z + (size_t)rbase * DI + cz) =
                        make_float2(fsilu(acc[mt][f][0]), fsilu(acc[mt][f][1]));
                    *(float2*)(Z + (size_t)(rbase + 8) * DI + cz) =
                        make_float2(fsilu(acc[mt][f][2]), fsilu(acc[mt][f][3]));
                }
                acc[mt][f][0] = acc[mt][f][1] = acc[mt][f][2] = acc[mt][f][3] = 0.f;
            }
    }
}

// ---------------- streamed bf16 hi/lo tensor-core GEMM ----------------
// MODE 3: C += A@B^T (residual e), then fused RMS -> Eh/El with nw
// MODE 4: C = A@B^T where A is computed inline: silu(causal_conv4(g_uraw)) hi/lo
template<int NTILE, int MODE>
__global__ void __launch_bounds__(256, 2) mma_gemm(
    const __nv_bfloat16* __restrict__ Ah, const __nv_bfloat16* __restrict__ Al, int lda,
    const __nv_bfloat16* __restrict__ Bh, const __nv_bfloat16* __restrict__ Bl, int ldb,
    float* __restrict__ C, int ldc, float* __restrict__ C2,
    __nv_bfloat16* __restrict__ Eh, __nv_bfloat16* __restrict__ El,
    const float* __restrict__ nw, const float* __restrict__ cw, const float* __restrict__ cb,
    int Nvalid, int K)
{
    constexpr int WARP_N = NTILE / 2;
    constexpr int NT8    = WARP_N / 8;
    constexpr int ASZ    = 2 * 128 * GP;
    constexpr int SS     = ASZ + 2 * NTILE * GP;
    extern __shared__ char smem[];
    const uint32_t sb = smem_u32(smem);
    const int tid  = threadIdx.x;
    const int wid  = tid >> 5, lane = tid & 31;
    const int row0 = blockIdx.y * 128;
    const int col0 = blockIdx.x * NTILE;
    const int m_off = (wid & 3) * 32;
    const int n_off = (wid >> 2) * WARP_N;

    const int j = lane >> 3, r = lane & 7;
    const int a_loff = ((j & 1) * 8 + r) * GP + (j >> 1) * 16;
    const int b_loff = ((j >> 1) * 8 + r) * GP + (j & 1) * 16;

    float acc[2][NT8][4];
    #pragma unroll
    for (int mt = 0; mt < 2; mt++)
        #pragma unroll
        for (int nt = 0; nt < NT8; nt++)
            #pragma unroll
            for (int i = 0; i < 4; i++) acc[mt][nt][i] = 0.f;

    auto stage = [&](int st, int k0) {
        uint32_t base = sb + st * SS;
        if (MODE != 4) {
            #pragma unroll
            for (int i = 0; i < 4; i++) {
                int idx = tid + i * 256;
                int h = idx >> 9, rr = (idx >> 2) & 127, c = idx & 3;
                const __nv_bfloat16* src = (h ? Al : Ah) + (size_t)(row0 + rr) * lda + k0 + c * 8;
                cp16(base + h * (128 * GP) + rr * GP + c * 16, src);
            }
        }
        #pragma unroll
        for (int i = 0; i < NTILE / 32; i++) {
            int idx = tid + i * 256;
            int h = idx >= NTILE * 4;
            int id2 = idx & (NTILE * 4 - 1);
            int n = id2 >> 2, c = id2 & 3;
            const __nv_bfloat16* src = (h ? Bl : Bh) + (size_t)(col0 + n) * ldb + k0 + c * 8;
            cp16(base + ASZ + h * (NTILE * GP) + n * GP + c * 16, src);
        }
        cp_commit();
    };

    auto convA = [&](int st, int k0) {
        uint32_t base = sb + st * SS;
        #pragma unroll
        for (int i = 0; i < 2; i++) {
            int idx = tid + i * 256;
            int rr = idx >> 2, c = idx & 3;
            int tok = row0 + rr;
            int mm = tok / NSEQ;
            int n  = tok - mm * NSEQ;
            int ch0 = k0 + c * 8;
            const float* up = g_uraw + (size_t)tok * DI + ch0;
            float t0[8], t1[8] = {0}, t2[8] = {0}, t3[8] = {0};
            *(float4*)(t0)     = *(const float4*)(up);
            *(float4*)(t0 + 4) = *(const float4*)(up + 4);
            if (n >= 1) { *(float4*)(t1) = *(const float4*)(up - DI);
                          *(float4*)(t1 + 4) = *(const float4*)(up - DI + 4); }
            if (n >= 2) { *(float4*)(t2) = *(const float4*)(up - 2 * DI);
                          *(float4*)(t2 + 4) = *(const float4*)(up - 2 * DI + 4); }
            if (n >= 3) { *(float4*)(t3) = *(const float4*)(up - 3 * DI);
                          *(float4*)(t3 + 4) = *(const float4*)(up - 3 * DI + 4); }
            float bias[8];
            *(float4*)(bias)     = *(const float4*)(cb + ch0);
            *(float4*)(bias + 4) = *(const float4*)(cb + ch0 + 4);
            float u[8];
            #pragma unroll
            for (int ch = 0; ch < 8; ch++) {
                float4 w = *(const float4*)(cw + (ch0 + ch) * DC);
                float uc = bias[ch];
                uc = fmaf(t3[ch], w.x, uc);
                uc = fmaf(t2[ch], w.y, uc);
                uc = fmaf(t1[ch], w.z, uc);
                uc = fmaf(t0[ch], w.w, uc);
                u[ch] = fsilu(uc);
            }
            uint2 hv, lv;
            hv.x = pack_hi2(u[0], u[1]); lv.x = pack_lo2(u[0], u[1], hv.x);
            hv.y = pack_hi2(u[2], u[3]); lv.y = pack_lo2(u[2], u[3], hv.y);
            *(uint2*)(smem + (base - sb) + rr * GP + c * 16) = hv;
            uint2 hv2, lv2;
            hv2.x = pack_hi2(u[4], u[5]); lv2.x = pack_lo2(u[4], u[5], hv2.x);
            hv2.y = pack_hi2(u[6], u[7]); lv2.y = pack_lo2(u[6], u[7], hv2.y);
            *(uint2*)(smem + (base - sb) + rr * GP + c * 16 + 8) = hv2;
            *(uint2*)(smem + (base - sb) + 128 * GP + rr * GP + c * 16)     = lv;
            *(uint2*)(smem + (base - sb) + 128 * GP + rr * GP + c * 16 + 8) = lv2;
        }
    };

    auto compute = [&](int i) {
        uint32_t base = sb + (i & 1) * SS;
        uint32_t sA[2] = { base, base + 128 * GP };
        uint32_t sB[2] = { base + ASZ, base + ASZ + NTILE * GP };
        #pragma unroll
        for (int kk = 0; kk < 32; kk += 16) {
            uint32_t afr[2][2][4];
            #pragma unroll
            for (int mt = 0; mt < 2; mt++)
                #pragma unroll
                for (int h = 0; h < 2; h++)
                    ldm4(afr[mt][h], sA[h] + (m_off + mt * 16) * GP + kk * 2 + a_loff);
            uint32_t bfr[NTILE / 32][2][4];
            #pragma unroll
            for (int np = 0; np < NTILE / 32; np++)
                #pragma unroll
                for (int h = 0; h < 2; h++)
                    ldm4(bfr[np][h], sB[h] + (n_off + np * 16) * GP + kk * 2 + b_loff);
            #pragma unroll
            for (int mt = 0; mt < 2; mt++)
                #pragma unroll
                for (int nt = 0; nt < NT8; nt++) {
                    const uint32_t* bh = &bfr[nt >> 1][0][(nt & 1) * 2];
                    const uint32_t* bl = &bfr[nt >> 1][1][(nt & 1) * 2];
                    mma16816(acc[mt][nt], afr[mt][0], bh);
                    mma16816(acc[mt][nt], afr[mt][0], bl);
                    mma16816(acc[mt][nt], afr[mt][1], bh);
                }
        }
    };

    const int nk = K / 32;
    stage(0, 0);
    for (int i = 0; i < nk; i++) {
        if (i + 1 < nk) {
            stage((i + 1) & 1, (i + 1) * 32);
            asm volatile("cp.async.wait_group 1;" ::: "memory");
        } else {
            asm volatile("cp.async.wait_group 0;" ::: "memory");
        }
        if (MODE == 4) convA(i & 1, i * 32);
        __syncthreads();
        compute(i);
        __syncthreads();
    }

    const int lr = lane >> 2, lq = lane & 3;
    if (MODE == 4) {
        #pragma unroll
        for (int mt = 0; mt < 2; mt++)
            #pragma unroll
            for (int nt = 0; nt < NT8; nt++) {
                int rbase = row0 + m_off + mt * 16 + lr;
                int cc = col0 + n_off + nt * 8 + lq * 2;
                if (cc < Nvalid) {
                    *(float2*)(C + (size_t)rbase * ldc + cc) =
                        make_float2(acc[mt][nt][0], acc[mt][nt][1]);
                    *(float2*)(C + (size_t)(rbase + 8) * ldc + cc) =
                        make_float2(acc[mt][nt][2], acc[mt][nt][3]);
                }
            }
    } else {  // MODE 3
        float* ssq = (float*)smem;
        const int half = wid >> 2;
        float part[4] = {0.f, 0.f, 0.f, 0.f};
        #pragma unroll
        for (int mt = 0; mt < 2; mt++)
            #pragma unroll
            for (int nt = 0; nt < NT8; nt++) {
                int r0g = row0 + m_off + mt * 16 + lr;
                int cc = n_off + nt * 8 + lq * 2;
                float2* p0 = (float2*)(C + (size_t)r0g * ldc + cc);
                float2* p1 = (float2*)(C + (size_t)(r0g + 8) * ldc + cc);
                float2 o0 = *p0, o1 = *p1;
                o0.x += acc[mt][nt][0]; o0.y += acc[mt][nt][1];
                o1.x += acc[mt][nt][2]; o1.y += acc[mt][nt][3];
                *p0 = o0; *p1 = o1;
                acc[mt][nt][0] = o0.x; acc[mt][nt][1] = o0.y;
                acc[mt][nt][2] = o1.x; acc[mt][nt][3] = o1.y;
                part[mt * 2 + 0] += o0.x * o0.x + o0.y * o0.y;
                part[mt * 2 + 1] += o1.x * o1.x + o1.y * o1.y;
            }
        #pragma unroll
        for (int s = 0; s < 4; s++) {
            part[s] += __shfl_xor_sync(0xffffffffu, part[s], 1);
            part[s] += __shfl_xor_sync(0xffffffffu, part[s], 2);
        }
        if (lq == 0) {
            ssq[half * 128 + m_off + lr]      = part[0];
            ssq[half * 128 + m_off + lr + 8]  = part[1];
            ssq[half * 128 + m_off + lr + 16] = part[2];
            ssq[half * 128 + m_off + lr + 24] = part[3];
        }
        __syncthreads();
        #pragma unroll
        for (int mt = 0; mt < 2; mt++) {
            int rr = m_off + mt * 16 + lr;
            float sc0 = rsqrtf((ssq[rr]     + ssq[128 + rr])     * (1.0f / DM) + 1e-5f);
            float sc1 = rsqrtf((ssq[rr + 8] + ssq[128 + rr + 8]) * (1.0f / DM) + 1e-5f);
            int r0g = row0 + rr;
            #pragma unroll
            for (int nt = 0; nt < NT8; nt++) {
                int cc = n_off + nt * 8 + lq * 2;
                float w0 = nw[cc], w1 = nw[cc + 1];
                float a0 = acc[mt][nt][0] * sc0 * w0, a1 = acc[mt][nt][1] * sc0 * w1;
                float a2 = acc[mt][nt][2] * sc1 * w0, a3 = acc[mt][nt][3] * sc1 * w1;
                uint32_t h0 = pack_hi2(a0, a1), l0 = pack_lo2(a0, a1, h0);
                uint32_t h1 = pack_hi2(a2, a3), l1 = pack_lo2(a2, a3, h1);
                *(uint32_t*)(Eh + (size_t)r0g * DM + cc)       = h0;
                *(uint32_t*)(El + (size_t)r0g * DM + cc)       = l0;
                *(uint32_t*)(Eh + (size_t)(r0g + 8) * DM + cc) = h1;
                *(uint32_t*)(El + (size_t)(r0g + 8) * DM + cc) = l1;
            }
        }
    }
}

// ---------------- weight convert+transpose ----------
__global__ void wconv_kernel(const float* __restrict__ src, __nv_bfloat16* __restrict__ dh,
                             __nv_bfloat16* __restrict__ dl, int K, int Nsrc, int Npad) {
    int l = blockIdx.y;
    src += (size_t)l * K * Nsrc;
    dh  += (size_t)l * Npad * K;
    dl  += (size_t)l * Npad * K;
    int idx = blockIdx.x * 256 + threadIdx.x;
    if (idx >= Npad * K) return;
    int n = idx / K, k = idx - n * K;
    float v = (n < Nsrc) ? src[(size_t)k * Nsrc + n] : 0.f;
    __nv_bfloat16 h = __float2bfloat16(v);
    dh[idx] = h;
    dl[idx] = __float2bfloat16(v - __bfloat162float(h));
}

// ---------------- 1) front ----------------
__global__ void front_kernel(const float* __restrict__ x,  const float* __restrict__ pw,
                             const float* __restrict__ pb, const float* __restrict__ lw,
                             const float* __restrict__ lb) {
    int row = blockIdx.x;
    int pd  = threadIdx.x;         // 64
    __shared__ float xr[DIN];
    __shared__ float red[2];
    if (pd < DIN) xr[pd] = x[row * DIN + pd];
    __syncthreads();
    float acc = pb[pd];
    #pragma unroll
    for (int i = 0; i < DIN; i++) acc = fmaf(xr[i], pw[i * PD + pd], acc);
    float s = acc;
    #pragma unroll
    for (int o = 16; o > 0; o >>= 1) s += __shfl_xor_sync(0xffffffffu, s, o);
    if ((pd & 31) == 0) red[pd >> 5] = s;
    __syncthreads();
    float mu = (red[0] + red[1]) * (1.0f / PD);
    __syncthreads();
    float d = acc - mu;
    float q = d * d;
    #pragma unroll
    for (int o = 16; o > 0; o >>= 1) q += __shfl_xor_sync(0xffffffffu, q, o);
    if ((pd & 31) == 0) red[pd >> 5] = q;
    __syncthreads();
    float var = (red[0] + red[1]) * (1.0f / PD);
    g_h[row * PD + pd] = d * rsqrtf(var + 1e-5f) * lw[pd] + lb[pd];
}

// ---------------- 2) patch embed + fused layer-0 RMS ----------------
__global__ void patch_kernel(const float* __restrict__ patch_w, const float* __restrict__ patch_b,
                             const float* __restrict__ nw0) {
    int n  = blockIdx.x;
    int m  = blockIdx.y;
    int dm = threadIdx.x;          // 128
    int b  = m >> 6, pd = m & 63;
    __shared__ float hv[PL];
    __shared__ float red[4];
    if (dm < PL) hv[dm] = g_h[(b * KSEQ + n * STR + dm) * PD + pd];
    __syncthreads();
    float acc = patch_b[dm];
    #pragma unroll
    for (int pl = 0; pl < PL; pl++) acc = fmaf(hv[pl], patch_w[pl * DM + dm], acc);
    size_t tok = (size_t)m * NSEQ + n;
    g_e[tok * DM + dm] = acc;
    float ss = block_reduce_128(acc * acc, red);
    float sc = rsqrtf(ss * (1.0f / DM) + 1e-5f);
    float a = acc * sc * nw0[dm];
    __nv_bfloat16 h = __float2bfloat16(a);
    g_rh[tok * DM + dm] = h;
    g_rl[tok * DM + dm] = __float2bfloat16(a - __bfloat162float(h));
}

// ---------------- 5) fused conv + dt-proj + softplus + scan + gate ----------
__global__ void scan_kernel(const float* __restrict__ dtw, const float* __restrict__ dtbp,
                            const float* __restrict__ alog, const float* __restrict__ dpp,
                            const float* __restrict__ cw, const float* __restrict__ cb) {
    __shared__ float ub[2][8 * DI];
    __shared__ float zb[2][8 * DI];
    __shared__ float db[2][8 * XPJ];
    int m = blockIdx.x;            // MSEQ
    int d = threadIdx.x;           // DI
    float wreg[DTR];
    #pragma unroll
    for (int i = 0; i < DTR; i++) wreg[i] = dtw[i * DI + d];
    float dtb = dtbp[d];
    float Dpv = dpp[d];
    float cw0 = cw[d * DC + 0], cw1 = cw[d * DC + 1], cw2 = cw[d * DC + 2], cw3 = cw[d * DC + 3];
    float cbv = cb[d];
    bool fast = true;
    #pragma unroll
    for (int s = 0; s < DS; s++) {
        float as = -fexp(alog[d * DS + s]);
        fast = fast && (fabsf(as + (float)(s + 1)) < 1e-3f);
    }
    float hst[DS];
    #pragma unroll
    for (int s = 0; s < DS; s++) hst[s] = 0.f;
    float x0 = 0.f, x1 = 0.f, x2 = 0.f;     // conv taps

    const float* ubase = g_uraw + (size_t)m * NSEQ * DI;
    const float* zbase = g_zg   + (size_t)m * NSEQ * DI;
    const float* dbase = g_dbc  + (size_t)m * NSEQ * XPJ;
    const uint32_t ub0 = smem_u32(ub), zb0 = smem_u32(zb), db0 = smem_u32(db);

    auto stage = [&](int buf, int t0, int cnt) {
        int nu = cnt * (DI / 4);                 // cp16 count for u (and z)
        for (int idx = d; idx < nu; idx += DI) {
            cp16(ub0 + buf * (8 * DI * 4) + idx * 16, ubase + (size_t)t0 * DI + idx * 4);
            cp16(zb0 + buf * (8 * DI * 4) + idx * 16, zbase + (size_t)t0 * DI + idx * 4);
        }
        int ndq = cnt * (XPJ / 4);
        for (int idx = d; idx < ndq; idx += DI)
            cp16(db0 + buf * (8 * XPJ * 4) + idx * 16, dbase + (size_t)t0 * XPJ + idx * 4);
        cp_commit();
    };

    stage(0, 0, 8);
    const int NTILES = (NSEQ + 7) / 8;   // 16
    for (int jt = 0; jt < NTILES; jt++) {
        int t0 = jt * 8;
        int cnt = min(8, NSEQ - t0);
        if (jt + 1 < NTILES) {
            stage((jt + 1) & 1, t0 + 8, min(8, NSEQ - t0 - 8));
            asm volatile("cp.async.wait_group 1;" ::: "memory");
        } else {
            asm volatile("cp.async.wait_group 0;" ::: "memory");
        }
        __syncthreads();
        int buf = jt & 1;
        for (int tt = 0; tt < cnt; tt++) {
            int t = t0 + tt;
            const float* s40 = &db[buf][tt * XPJ];
            size_t off = ((size_t)m * NSEQ + t) * DI + d;
            // inline conv + silu (from smem-staged uraw)
            float xt = ub[buf][tt * DI + d];
            float uc = cbv;
            uc = fmaf(x0, cw0, uc);
            uc = fmaf(x1, cw1, uc);
            uc = fmaf(x2, cw2, uc);
            uc = fmaf(xt, cw3, uc);
            x0 = x1; x1 = x2; x2 = xt;
            float u_td = uc * frcp_fast(1.0f + __expf(-uc));
            // dt-proj + softplus
            float v = dtb;
            #pragma unroll
            for (int i = 0; i < DTR; i++) v = fmaf(s40[i], wreg[i], v);
            float e1 = __expf(v);
            float delta = (v > 20.f) ? v : __logf(1.0f + e1);
            float du = delta * u_td;
            float y;
            if (fast) {
                float rr = frcp_fast(1.0f + e1);     // exp(-softplus(v))
                float pw[DS];
                pw[0] = rr;
                #pragma unroll
                for (int s = 1; s < DS; s++) pw[s] = pw[s >> 1] * pw[(s - 1) >> 1];
                float y0 = 0.f, y1 = 0.f, y2 = 0.f, y3 = 0.f;
                #pragma unroll
                for (int s = 0; s < DS; s += 4) {
                    hst[s]     = fmaf(pw[s],     hst[s],     du * s40[DTR + s]);
                    hst[s + 1] = fmaf(pw[s + 1], hst[s + 1], du * s40[DTR + s + 1]);
                    hst[s + 2] = fmaf(pw[s + 2], hst[s + 2], du * s40[DTR + s + 2]);
                    hst[s + 3] = fmaf(pw[s + 3], hst[s + 3], du * s40[DTR + s + 3]);
                    y0 = fmaf(hst[s],     s40[DTR + DS + s],     y0);
                    y1 = fmaf(hst[s + 1], s40[DTR + DS + s + 1], y1);
                    y2 = fmaf(hst[s + 2], s40[DTR + DS + s + 2], y2);
                    y3 = fmaf(hst[s + 3], s40[DTR + DS + s + 3], y3);
                }
                y = (y0 + y1) + (y2 + y3);
            } else {
                y = 0.f;
                #pragma unroll
                for (int s = 0; s < DS; s++) {
                    float as = -fexp(alog[d * DS + s]);
                    float dA = fexp(delta * as);
                    hst[s] = fmaf(dA, hst[s], du * s40[DTR + s]);
                    y = fmaf(hst[s], s40[DTR + DS + s], y);
                }
            }
            float yo = fmaf(u_td, Dpv, y);
            float yg = yo * zb[buf][tt * DI + d];
            __nv_bfloat16 h = __float2bfloat16(yg);
            g_ah[off] = h;
            g_al[off] = __float2bfloat16(yg - __bfloat162float(h));
        }
        __syncthreads();
    }
}

// ---------------- 6) final RMS + bb dot (warp-per-token) ----------------
__global__ void bb_kernel(const float* __restrict__ fnw, const float* __restrict__ bbw,
                          const float* __restrict__ bbb) {
    int m = blockIdx.x;
    int tid = threadIdx.x;         // 128
    int w = tid >> 5, lane = tid & 31;
    __shared__ float red[4];
    float4 fw = *(const float4*)(fnw + lane * 4);
    float acc0 = 0.f, acc1 = 0.f, acc2 = 0.f, acc3 = 0.f;
    for (int n = w; n < NSEQ; n += 4) {
        const float* er = g_e + ((size_t)m * NSEQ + n) * DM;
        float4 v = *(const float4*)(er + lane * 4);
        float ss = v.x * v.x + v.y * v.y + v.z * v.z + v.w * v.w;
        #pragma unroll
        for (int o = 16; o > 0; o >>= 1) ss += __shfl_xor_sync(0xffffffffu, ss, o);
        float sc = rsqrtf(ss * (1.0f / DM) + 1e-5f);
        float4 bw = *(const float4*)(bbw + n * DM + lane * 4);
        acc0 = fmaf(v.x * sc * fw.x, bw.x, acc0);
        acc1 = fmaf(v.y * sc * fw.y, bw.y, acc1);
        acc2 = fmaf(v.z * sc * fw.z, bw.z, acc2);
        acc3 = fmaf(v.w * sc * fw.w, bw.w, acc3);
    }
    float tot = acc0 + acc1 + acc2 + acc3;
    #pragma unroll
    for (int o = 16; o > 0; o >>= 1) tot += __shfl_xor_sync(0xffffffffu, tot, o);
    if (lane == 0) red[w] = tot;
    __syncthreads();
    if (tid == 0) g_y1[m] = red[0] + red[1] + red[2] + red[3] + bbb[0];
}

// ---------------- 7) head ----------------
__global__ void head_kernel(const float* __restrict__ hw, const float* __restrict__ hb,
                            float* __restrict__ out) {
    int t = threadIdx.x;           // 64
    int b = t >> 1, jj = t & 1;
    float acc = hb[jj];
    #pragma unroll
    for (int p = 0; p < PD; p++) acc = fmaf(g_y1[b * PD + p], hw[p * 2 + jj], acc);
    out[b * 2 + jj] = acc;
}

// ---------------- launch ----------------
extern "C" void kernel_launch(void* const* d_in, const int* in_sizes, int n_in,
                              void* d_out, int out_size) {
    const float* x       = (const float*)d_in[0];
    const float* proj_w  = (const float*)d_in[1];
    const float* proj_b  = (const float*)d_in[2];
    const float* ln_w    = (const float*)d_in[3];
    const float* ln_b    = (const float*)d_in[4];
    const float* patch_w = (const float*)d_in[5];
    const float* patch_b = (const float*)d_in[6];
    const float* in_w    = (const float*)d_in[7];
    const float* conv_w  = (const float*)d_in[8];
    const float* conv_b  = (const float*)d_in[9];
    const float* xproj_w = (const float*)d_in[10];
    const float* dt_w    = (const float*)d_in[11];
    const float* dt_b    = (const float*)d_in[12];
    const float* A_log   = (const float*)d_in[13];
    const float* Dp      = (const float*)d_in[14];
    const float* out_w   = (const float*)d_in[15];
    const float* norm_w  = (const float*)d_in[16];
    const float* fnorm_w = (const float*)d_in[17];
    const float* bb_w    = (const float*)d_in[18];
    const float* bb_b    = (const float*)d_in[19];
    const float* head_w  = (const float*)d_in[20];
    const float* head_b  = (const float*)d_in[21];
    float* out = (float*)d_out;

    float *uraw, *zg, *dbc, *e;
    __nv_bfloat16 *rh, *rl, *ah, *al, *wih, *wil, *wxh, *wxl, *woh, *wol;
    cudaGetSymbolAddress((void**)&uraw, g_uraw);
    cudaGetSymbolAddress((void**)&zg,  g_zg);
    cudaGetSymbolAddress((void**)&dbc, g_dbc);
    cudaGetSymbolAddress((void**)&e,   g_e);
    cudaGetSymbolAddress((void**)&rh,  g_rh);
    cudaGetSymbolAddress((void**)&rl,  g_rl);
    cudaGetSymbolAddress((void**)&ah,  g_ah);
    cudaGetSymbolAddress((void**)&al,  g_al);
    cudaGetSymbolAddress((void**)&wih, g_wih);
    cudaGetSymbolAddress((void**)&wil, g_wil);
    cudaGetSymbolAddress((void**)&wxh, g_wxh);
    cudaGetSymbolAddress((void**)&wxl, g_wxl);
    cudaGetSymbolAddress((void**)&woh, g_woh);
    cudaGetSymbolAddress((void**)&wol, g_wol);

    const int SMEM128 = 2 * (20480 + 2 * 128 * GP);   // 81920
    const int SMEM64  = 2 * (20480 + 2 * 64 * GP);    // 61440
    const int SMEM_IN = 2 * 128 * 272 + 2 * 20480;    // 110592
    cudaFuncSetAttribute(inproj_gemm,      cudaFuncAttributeMaxDynamicSharedMemorySize, SMEM_IN);
    cudaFuncSetAttribute(mma_gemm<128, 3>, cudaFuncAttributeMaxDynamicSharedMemorySize, SMEM128);
    cudaFuncSetAttribute(mma_gemm<64,  4>, cudaFuncAttributeMaxDynamicSharedMemorySize, SMEM64);

    wconv_kernel<<<dim3((2 * DI * DM + 255) / 256, NL), 256>>>(in_w, wih, wil, DM, 2 * DI, 2 * DI);
    wconv_kernel<<<dim3((64 * DI + 255) / 256, NL), 256>>>(xproj_w, wxh, wxl, DI, XPJ, 64);
    wconv_kernel<<<dim3((DM * DI + 255) / 256, NL), 256>>>(out_w, woh, wol, DI, DM, DM);

    front_kernel<<<BATCH * KSEQ, PD>>>(x, proj_w, proj_b, ln_w, ln_b);
    patch_kernel<<<dim3(NSEQ, MSEQ), DM>>>(patch_w, patch_b, norm_w);

    for (int l = 0; l < NL; l++) {
        const float* cwl = conv_w + (size_t)l * DI * DC;
        const float* cbl = conv_b + (size_t)l * DI;
        // uz = rms(e) @ in_w[l]; A-resident, split epilogue -> u_raw + silu(z)
        inproj_gemm<<<NTOK / 128, 256, SMEM_IN>>>(
            rh, rl, wih + (size_t)l * 2 * DI * DM, wil + (size_t)l * 2 * DI * DM, uraw, zg);
        // dbc = silu(conv(uraw)) @ xproj_w[l]  (conv fused into A-staging)
        mma_gemm<64, 4><<<dim3(1, NTOK / 128), 256, SMEM64>>>(
            nullptr, nullptr, DI, wxh + (size_t)l * 64 * DI, wxl + (size_t)l * 64 * DI, DI,
            dbc, XPJ, nullptr, nullptr, nullptr, nullptr, cwl, cbl, XPJ, DI);
        // scan (conv fused inline, cp.async staged inputs)
        scan_kernel<<<MSEQ, DI>>>(dt_w + (size_t)l * DTR * DI, dt_b + (size_t)l * DI,
                                  A_log + (size_t)l * DI * DS, Dp + (size_t)l * DI, cwl, cbl);
        // e += y @ out_w[l]; fused rms for next layer -> rh/rl
        const float* nwn = norm_w + ((l + 1) % NL) * DM;
        mma_gemm<128, 3><<<dim3(1, NTOK / 128), 256, SMEM128>>>(
            ah, al, DI, woh + (size_t)l * DM * DI, wol + (size_t)l * DM * DI, DI,
            e, DM, nullptr, rh, rl, nwn, nullptr, nullptr, DM, DI);
    }

    bb_kernel<<<MSEQ, DM>>>(fnorm_w, bb_w, bb_b);
    head_kernel<<<1, 64>>>(head_w, head_b, out);
}